// round 1
// baseline (speedup 1.0000x reference)
#include <cuda_runtime.h>
#include <math.h>

// Problem constants
#define BB 4
#define NN 2048
#define CC 1024
#define HH 16
#define HD 64
#define M_TOT (BB*NN)    // 8192
#define N3C   (3*CC)     // 3072
#define K_TOT CC         // 1024

// Scratch (static device globals — allocation-free per harness rules)
__device__ float g_x[M_TOT * CC];          // x = inputs + PE   [8192,1024]
__device__ float g_q[BB*HH*NN*HD];         // [B,H,N,hd]
__device__ float g_k[BB*HH*NN*HD];
__device__ float g_v[BB*HH*NN*HD];

// ---------------------------------------------------------------------------
// Kernel 1: x = inputs + sinusoidal PE (PE depends only on (n,c); loop over b)
// ---------------------------------------------------------------------------
__global__ void pe_add_kernel(const float* __restrict__ in) {
    int idx = blockIdx.x * blockDim.x + threadIdx.x;   // over N*C
    if (idx >= NN * CC) return;
    int c = idx & (CC - 1);
    int n = idx >> 10;
    float e = (float)(2 * (c >> 1)) / (float)CC;
    float rate = powf(10000.0f, -e);                   // accurate powf
    float ang = (float)n * rate;
    float s, co;
    sincosf(ang, &s, &co);                             // accurate range reduction
    float pe = (c & 1) ? co : s;
#pragma unroll
    for (int b = 0; b < BB; b++) {
        g_x[b * (NN * CC) + idx] = in[b * (NN * CC) + idx] + pe;
    }
}

// ---------------------------------------------------------------------------
// Kernel 2: QKV GEMM  [8192,1024] x [1024,3072] -> scatter into Q/K/V [B,H,N,hd]
// 128x128 tile, TK=8, 256 threads, 8x8 per thread.
// ---------------------------------------------------------------------------
#define GTM 128
#define GTN 128
#define GTK 8
#define GPAD 4
#define GSTR (GTM + GPAD)   // 132, keeps float4 alignment (132*4 % 16 == 0)

__global__ __launch_bounds__(256) void qkv_gemm_kernel(const float* __restrict__ W) {
    __shared__ float As[GTK][GSTR];   // A tile transposed: As[k][m]
    __shared__ float Bs[GTK][GSTR];   // B tile: Bs[k][n]

    const int tid = threadIdx.x;
    const int tx = tid & 15;          // 0..15
    const int ty = tid >> 4;          // 0..15
    const int row0 = blockIdx.y * GTM;
    const int col0 = blockIdx.x * GTN;

    float acc[8][8];
#pragma unroll
    for (int i = 0; i < 8; i++)
#pragma unroll
        for (int j = 0; j < 8; j++) acc[i][j] = 0.0f;

    for (int k0 = 0; k0 < K_TOT; k0 += GTK) {
        // Load A tile 128x8 (transposed into smem)
#pragma unroll
        for (int p = 0; p < 4; p++) {
            int idx = p * 256 + tid;
            int kk = idx & 7;
            int mm = idx >> 3;
            As[kk][mm] = g_x[(size_t)(row0 + mm) * K_TOT + k0 + kk];
        }
        // Load B tile 8x128
#pragma unroll
        for (int p = 0; p < 4; p++) {
            int idx = p * 256 + tid;
            int cc2 = idx & 127;
            int kr  = idx >> 7;
            Bs[kr][cc2] = W[(size_t)(k0 + kr) * N3C + col0 + cc2];
        }
        __syncthreads();

#pragma unroll
        for (int k = 0; k < GTK; k++) {
            float4 a0 = *(const float4*)&As[k][ty * 8];
            float4 a1 = *(const float4*)&As[k][ty * 8 + 4];
            float4 b0 = *(const float4*)&Bs[k][tx * 8];
            float4 b1 = *(const float4*)&Bs[k][tx * 8 + 4];
            float a[8] = {a0.x, a0.y, a0.z, a0.w, a1.x, a1.y, a1.z, a1.w};
            float b[8] = {b0.x, b0.y, b0.z, b0.w, b1.x, b1.y, b1.z, b1.w};
#pragma unroll
            for (int i = 0; i < 8; i++)
#pragma unroll
                for (int j = 0; j < 8; j++) acc[i][j] = fmaf(a[i], b[j], acc[i][j]);
        }
        __syncthreads();
    }

    // Epilogue: scatter into Q/K/V [B,H,N,hd].
    // col = t*1024 + h*64 + d   (t = which of q/k/v)
#pragma unroll
    for (int i = 0; i < 8; i++) {
        int row = row0 + ty * 8 + i;
        int b = row >> 11;          // /2048
        int n = row & (NN - 1);
#pragma unroll
        for (int j = 0; j < 8; j++) {
            int col = col0 + tx * 8 + j;
            int t = col >> 10;
            int h = (col >> 6) & 15;
            int d = col & 63;
            float* dst = (t == 0) ? g_q : ((t == 1) ? g_k : g_v);
            dst[(((size_t)(b * HH + h)) * NN + n) * HD + d] = acc[i][j];
        }
    }
}

// ---------------------------------------------------------------------------
// Kernel 3: Flash attention per (b,h). BM=64 query rows, BN=64 keys/tile.
// 256 threads, 4x4 per-thread tiles. K stored transposed; P reuses K buffer.
// logits = (q.k)*scale - mq[n]*mk[m]; online softmax.
// ---------------------------------------------------------------------------
#define ABM 64
#define ABN 64
#define KPSTR 65   // K-transposed / P buffer stride

__global__ __launch_bounds__(256) void attn_kernel(const float* __restrict__ mask,
                                                   float* __restrict__ out) {
    extern __shared__ float sm[];
    float* Qs  = sm;                 // [64][64]   stride 64
    float* Vs  = Qs + ABM * HD;      // [64][64]   stride 64
    float* KPs = Vs + ABN * HD;      // [64][65]   K^T [d][c] then P [r][m]
    float* mq  = KPs + HD * KPSTR;   // [64]
    float* mk  = mq + ABM;           // [64]

    const int bh = blockIdx.y;
    const int b  = bh >> 4;
    const int h  = bh & 15;
    const int r0 = blockIdx.x * ABM;

    const int tid = threadIdx.x;
    const int tx = tid & 15;   // col group
    const int ty = tid >> 4;   // row group

    const float* Qg = g_q + (size_t)bh * NN * HD;
    const float* Kg = g_k + (size_t)bh * NN * HD;
    const float* Vg = g_v + (size_t)bh * NN * HD;

    // Load Q tile (64x64) + row mask
#pragma unroll
    for (int p = 0; p < 16; p++) {
        int idx = p * 256 + tid;
        int r = idx >> 6, d = idx & 63;
        Qs[r * HD + d] = Qg[(size_t)(r0 + r) * HD + d];
    }
    if (tid < ABM) mq[tid] = mask[b * NN + r0 + tid];

    float m_i[4], l_i[4], acc[4][4];
#pragma unroll
    for (int i = 0; i < 4; i++) {
        m_i[i] = -1e30f;
        l_i[i] = 0.0f;
#pragma unroll
        for (int j = 0; j < 4; j++) acc[i][j] = 0.0f;
    }
    const float scale = 0.125f;  // 64^-0.5

    for (int c0 = 0; c0 < NN; c0 += ABN) {
        __syncthreads();  // Q ready (iter 0) / prev-tile P & V reads done
        // Load K (transposed: KPs[d][c]) and V (row-major)
#pragma unroll
        for (int p = 0; p < 16; p++) {
            int idx = p * 256 + tid;
            int r = idx >> 6, d = idx & 63;
            float kv = Kg[(size_t)(c0 + r) * HD + d];
            KPs[d * KPSTR + r] = kv;
            Vs[r * HD + d] = Vg[(size_t)(c0 + r) * HD + d];
        }
        if (tid < ABN) mk[tid] = mask[b * NN + c0 + tid];
        __syncthreads();

        // S = Q K^T  (per thread: rows ty*4+i, cols tx*4+j)
        float s[4][4];
#pragma unroll
        for (int i = 0; i < 4; i++)
#pragma unroll
            for (int j = 0; j < 4; j++) s[i][j] = 0.0f;

#pragma unroll 8
        for (int k = 0; k < HD; k++) {
            float a[4], kb[4];
#pragma unroll
            for (int i = 0; i < 4; i++) a[i] = Qs[(ty * 4 + i) * HD + k];
#pragma unroll
            for (int j = 0; j < 4; j++) kb[j] = KPs[k * KPSTR + tx * 4 + j];
#pragma unroll
            for (int i = 0; i < 4; i++)
#pragma unroll
                for (int j = 0; j < 4; j++) s[i][j] = fmaf(a[i], kb[j], s[i][j]);
        }

        float mqv[4], mkv[4];
#pragma unroll
        for (int i = 0; i < 4; i++) mqv[i] = mq[ty * 4 + i];
#pragma unroll
        for (int j = 0; j < 4; j++) mkv[j] = mk[tx * 4 + j];
#pragma unroll
        for (int i = 0; i < 4; i++)
#pragma unroll
            for (int j = 0; j < 4; j++)
                s[i][j] = s[i][j] * scale - mqv[i] * mkv[j];

        // Online softmax update
        float p[4][4];
#pragma unroll
        for (int i = 0; i < 4; i++) {
            float mx = s[i][0];
#pragma unroll
            for (int j = 1; j < 4; j++) mx = fmaxf(mx, s[i][j]);
#pragma unroll
            for (int off = 8; off; off >>= 1)
                mx = fmaxf(mx, __shfl_xor_sync(0xffffffffu, mx, off, 16));
            float mnew = fmaxf(m_i[i], mx);
            float fac = __expf(m_i[i] - mnew);
            float rs = 0.0f;
#pragma unroll
            for (int j = 0; j < 4; j++) {
                p[i][j] = __expf(s[i][j] - mnew);
                rs += p[i][j];
            }
#pragma unroll
            for (int off = 8; off; off >>= 1)
                rs += __shfl_xor_sync(0xffffffffu, rs, off, 16);
            l_i[i] = l_i[i] * fac + rs;
            m_i[i] = mnew;
#pragma unroll
            for (int j = 0; j < 4; j++) acc[i][j] *= fac;
        }

        __syncthreads();  // everyone done reading KPs as K
        // Write P into KPs buffer (now [r][m], stride 65)
#pragma unroll
        for (int i = 0; i < 4; i++)
#pragma unroll
            for (int j = 0; j < 4; j++)
                KPs[(ty * 4 + i) * KPSTR + tx * 4 + j] = p[i][j];
        __syncthreads();

        // O += P V
#pragma unroll 4
        for (int m2 = 0; m2 < ABN; m2++) {
            float pv[4], vv[4];
#pragma unroll
            for (int i = 0; i < 4; i++) pv[i] = KPs[(ty * 4 + i) * KPSTR + m2];
#pragma unroll
            for (int j = 0; j < 4; j++) vv[j] = Vs[m2 * HD + tx * 4 + j];
#pragma unroll
            for (int i = 0; i < 4; i++)
#pragma unroll
                for (int j = 0; j < 4; j++) acc[i][j] = fmaf(pv[i], vv[j], acc[i][j]);
        }
    }

    // Write output: out[b][n][h*64+d], normalized by l
#pragma unroll
    for (int i = 0; i < 4; i++) {
        int n = r0 + ty * 4 + i;
        float inv = 1.0f / l_i[i];
#pragma unroll
        for (int j = 0; j < 4; j++) {
            out[((size_t)(b * NN + n)) * CC + h * HD + tx * 4 + j] = acc[i][j] * inv;
        }
    }
}

// ---------------------------------------------------------------------------
extern "C" void kernel_launch(void* const* d_in, const int* in_sizes, int n_in,
                              void* d_out, int out_size) {
    const float* inputs = (const float*)d_in[0];   // [B,N,C]
    const float* mask   = (const float*)d_in[1];   // [B,N]
    const float* W      = (const float*)d_in[2];   // [C,3C]
    float* out = (float*)d_out;                    // [B,N,C]

    // 49,920 B dynamic smem for attn (3 tiles + masks). Not a stream op;
    // safe under graph capture. Called every launch (idempotent, no guards).
    const int attn_smem = (ABM*HD + ABN*HD + HD*KPSTR + ABM + ABN) * (int)sizeof(float);
    cudaFuncSetAttribute((const void*)attn_kernel,
                         cudaFuncAttributeMaxDynamicSharedMemorySize, attn_smem);

    pe_add_kernel<<<(NN * CC + 255) / 256, 256>>>(inputs);
    qkv_gemm_kernel<<<dim3(N3C / GTN, M_TOT / GTM), 256>>>(W);
    attn_kernel<<<dim3(NN / ABM, BB * HH), 256, attn_smem>>>(mask, out);
}

// round 3
// speedup vs baseline: 3.3419x; 3.3419x over previous
#include <cuda_runtime.h>
#include <math.h>
#include <stdint.h>

// Problem constants
#define BB 4
#define NN 2048
#define CC 1024
#define HH 16
#define HD 64
#define M_TOT (BB*NN)    // 8192
#define N3C   (3*CC)     // 3072
#define K_TOT CC         // 1024

// Scratch (static device globals — allocation-free per harness rules)
__device__ float g_x [M_TOT * CC];         // x = inputs + PE (tf32-rounded) [8192,1024]
__device__ float g_wt[N3C * CC];           // W^T (tf32-rounded)            [3072,1024]
__device__ float g_q[BB*HH*NN*HD];         // [B,H,N,hd]
__device__ float g_k[BB*HH*NN*HD];
__device__ float g_v[BB*HH*NN*HD];

// ---------------------------------------------------------------------------
// Helpers: tf32 rounding + m16n8k8 tf32 mma (legacy tensor-core path; the
// harness toolchain targets base sm_103 where tcgen05 is unavailable).
// ---------------------------------------------------------------------------
__device__ __forceinline__ float to_tf32(float v) {
    uint32_t r;
    asm("cvt.rna.tf32.f32 %0, %1;" : "=r"(r) : "f"(v));
    return __uint_as_float(r);
}

__device__ __forceinline__ void mma_tf32(float* c, const uint32_t* a,
                                         uint32_t b0, uint32_t b1) {
    asm volatile(
        "mma.sync.aligned.m16n8k8.row.col.f32.tf32.tf32.f32 "
        "{%0,%1,%2,%3}, {%4,%5,%6,%7}, {%8,%9}, {%0,%1,%2,%3};"
        : "+f"(c[0]), "+f"(c[1]), "+f"(c[2]), "+f"(c[3])
        : "r"(a[0]), "r"(a[1]), "r"(a[2]), "r"(a[3]), "r"(b0), "r"(b1));
}

// ---------------------------------------------------------------------------
// Kernel 1: x = inputs + sinusoidal PE, rounded to tf32 (rna)
// ---------------------------------------------------------------------------
__global__ void pe_add_kernel(const float* __restrict__ in) {
    int idx = blockIdx.x * blockDim.x + threadIdx.x;   // over N*C
    if (idx >= NN * CC) return;
    int c = idx & (CC - 1);
    int n = idx >> 10;
    float e = (float)(2 * (c >> 1)) / (float)CC;
    float rate = powf(10000.0f, -e);
    float ang = (float)n * rate;
    float s, co;
    sincosf(ang, &s, &co);
    float pe = (c & 1) ? co : s;
#pragma unroll
    for (int b = 0; b < BB; b++) {
        g_x[b * (NN * CC) + idx] = to_tf32(in[b * (NN * CC) + idx] + pe);
    }
}

// ---------------------------------------------------------------------------
// Kernel 1b: W^T (tf32-rounded). W [1024,3072] -> g_wt [3072,1024]
// ---------------------------------------------------------------------------
__global__ __launch_bounds__(256) void wt_kernel(const float* __restrict__ W) {
    __shared__ float t[32][33];
    int tx = threadIdx.x, ty = threadIdx.y;
    int n0 = blockIdx.x * 32;   // over 3072
    int k0 = blockIdx.y * 32;   // over 1024
#pragma unroll
    for (int i = 0; i < 32; i += 8)
        t[ty + i][tx] = W[(size_t)(k0 + ty + i) * N3C + n0 + tx];
    __syncthreads();
#pragma unroll
    for (int i = 0; i < 32; i += 8)
        g_wt[(size_t)(n0 + ty + i) * K_TOT + k0 + tx] = to_tf32(t[tx][ty + i]);
}

// ---------------------------------------------------------------------------
// Kernel 2: QKV GEMM with mma.sync tf32.
// CTA tile 128x128, BK=16, 8 warps: 2(M)x4(N), warp tile 64x32.
// A = g_x [M,K] K-major, B = g_wt [N,K] K-major. Epilogue scatters to Q/K/V.
// smem strides of 20 floats make fragment LDS conflict-free.
// ---------------------------------------------------------------------------
#define GBM 128
#define GBN 128
#define GBK 16
#define GSTR 20
#define GNKT (K_TOT / GBK)      // 64

__global__ __launch_bounds__(256) void qkv_mma_kernel() {
    __shared__ float As[2][GBM][GSTR];
    __shared__ float Bs[2][GBN][GSTR];

    const int tid  = threadIdx.x;
    const int wid  = tid >> 5;
    const int lane = tid & 31;
    const int ty4  = lane >> 2;   // 0..7
    const int tx4  = lane & 3;    // 0..3
    const int wm   = (wid & 1) * 64;
    const int wn   = (wid >> 1) * 32;
    const int row0 = blockIdx.y * GBM;
    const int col0 = blockIdx.x * GBN;

    const int ra = tid >> 2;          // 0..63 (load row)
    const int c4 = (tid & 3) * 4;     // 0/4/8/12 (load col)

    float acc[4][4][4];
#pragma unroll
    for (int mi = 0; mi < 4; mi++)
#pragma unroll
        for (int ni = 0; ni < 4; ni++)
#pragma unroll
            for (int j = 0; j < 4; j++) acc[mi][ni][j] = 0.0f;

    float4 av0, av1, bv0, bv1;
    // preload tile 0
    av0 = *(const float4*)&g_x [(size_t)(row0 + ra)      * K_TOT + c4];
    av1 = *(const float4*)&g_x [(size_t)(row0 + ra + 64) * K_TOT + c4];
    bv0 = *(const float4*)&g_wt[(size_t)(col0 + ra)      * K_TOT + c4];
    bv1 = *(const float4*)&g_wt[(size_t)(col0 + ra + 64) * K_TOT + c4];
    {
        float* pa0 = &As[0][ra][c4];      pa0[0]=av0.x; pa0[1]=av0.y; pa0[2]=av0.z; pa0[3]=av0.w;
        float* pa1 = &As[0][ra + 64][c4]; pa1[0]=av1.x; pa1[1]=av1.y; pa1[2]=av1.z; pa1[3]=av1.w;
        float* pb0 = &Bs[0][ra][c4];      pb0[0]=bv0.x; pb0[1]=bv0.y; pb0[2]=bv0.z; pb0[3]=bv0.w;
        float* pb1 = &Bs[0][ra + 64][c4]; pb1[0]=bv1.x; pb1[1]=bv1.y; pb1[2]=bv1.z; pb1[3]=bv1.w;
    }
    __syncthreads();

    for (int kt = 0; kt < GNKT; kt++) {
        const int s = kt & 1;
        if (kt + 1 < GNKT) {
            const int k0 = (kt + 1) * GBK;
            av0 = *(const float4*)&g_x [(size_t)(row0 + ra)      * K_TOT + k0 + c4];
            av1 = *(const float4*)&g_x [(size_t)(row0 + ra + 64) * K_TOT + k0 + c4];
            bv0 = *(const float4*)&g_wt[(size_t)(col0 + ra)      * K_TOT + k0 + c4];
            bv1 = *(const float4*)&g_wt[(size_t)(col0 + ra + 64) * K_TOT + k0 + c4];
        }

#pragma unroll
        for (int ks = 0; ks < 2; ks++) {
            const int k0 = ks * 8;
            uint32_t af[4][4];
#pragma unroll
            for (int mi = 0; mi < 4; mi++) {
                const int r = wm + mi * 16 + ty4;
                af[mi][0] = __float_as_uint(As[s][r    ][k0 + tx4]);
                af[mi][1] = __float_as_uint(As[s][r + 8][k0 + tx4]);
                af[mi][2] = __float_as_uint(As[s][r    ][k0 + tx4 + 4]);
                af[mi][3] = __float_as_uint(As[s][r + 8][k0 + tx4 + 4]);
            }
            uint32_t bf[4][2];
#pragma unroll
            for (int ni = 0; ni < 4; ni++) {
                const int cn = wn + ni * 8 + ty4;
                bf[ni][0] = __float_as_uint(Bs[s][cn][k0 + tx4]);
                bf[ni][1] = __float_as_uint(Bs[s][cn][k0 + tx4 + 4]);
            }
#pragma unroll
            for (int mi = 0; mi < 4; mi++)
#pragma unroll
                for (int ni = 0; ni < 4; ni++)
                    mma_tf32(acc[mi][ni], af[mi], bf[ni][0], bf[ni][1]);
        }
        __syncthreads();
        if (kt + 1 < GNKT) {
            const int d = s ^ 1;
            float* pa0 = &As[d][ra][c4];      pa0[0]=av0.x; pa0[1]=av0.y; pa0[2]=av0.z; pa0[3]=av0.w;
            float* pa1 = &As[d][ra + 64][c4]; pa1[0]=av1.x; pa1[1]=av1.y; pa1[2]=av1.z; pa1[3]=av1.w;
            float* pb0 = &Bs[d][ra][c4];      pb0[0]=bv0.x; pb0[1]=bv0.y; pb0[2]=bv0.z; pb0[3]=bv0.w;
            float* pb1 = &Bs[d][ra + 64][c4]; pb1[0]=bv1.x; pb1[1]=bv1.y; pb1[2]=bv1.z; pb1[3]=bv1.w;
            __syncthreads();
        }
    }

    // Epilogue: scatter to Q/K/V [B,H,N,hd]
#pragma unroll
    for (int mi = 0; mi < 4; mi++) {
        const int row = row0 + wm + mi * 16 + ty4;   // and row+8
        const int b = row >> 11;
        const int n = row & (NN - 1);
#pragma unroll
        for (int ni = 0; ni < 4; ni++) {
            const int col = col0 + wn + ni * 8 + tx4 * 2;
            const int t = col >> 10;
            const int h = (col >> 6) & 15;
            const int d = col & 63;
            float* base = (t == 0) ? g_q : ((t == 1) ? g_k : g_v);
            float* p0 = base + (((size_t)(b * HH + h)) * NN + n) * HD + d;
            ((float2*)p0)[0] = make_float2(acc[mi][ni][0], acc[mi][ni][1]);
            float* p1 = base + (((size_t)(b * HH + h)) * NN + n + 8) * HD + d;
            ((float2*)p1)[0] = make_float2(acc[mi][ni][2], acc[mi][ni][3]);
        }
    }
}

// ---------------------------------------------------------------------------
// Kernel 3: Flash attention with mma.sync tf32.
// CTA = (b,h, 128 query rows); 8 warps x 16 rows. Key tiles of 64.
// S = Q K^T and O += P V on tensor cores; online softmax on C-fragments.
// smem strides: 68 for A-operands (Qs,Ps) & Ks; 72 for Vs (all conflict-free).
// ---------------------------------------------------------------------------
#define FBM 128
#define FBN 64
#define STR_A 68
#define STR_V 72
// float offsets into dynamic smem
#define OFF_Q  0
#define OFF_P  (OFF_Q + FBM*STR_A)          // 8704
#define OFF_K  (OFF_P + FBM*STR_A)          // 17408
#define OFF_V  (OFF_K + FBN*STR_A)          // 21760
#define OFF_MQ (OFF_V + FBN*STR_V)          // 26368
#define OFF_MK (OFF_MQ + FBM)               // 26496
#define FSM_FLOATS (OFF_MK + FBN)           // 26560
#define FSM_BYTES  (FSM_FLOATS * 4)         // 106240

__global__ __launch_bounds__(256) void attn_mma_kernel(const float* __restrict__ mask,
                                                       float* __restrict__ out) {
    extern __shared__ float smf[];
    float* Qs = smf + OFF_Q;
    float* Ps = smf + OFF_P;
    float* Ks = smf + OFF_K;
    float* Vs = smf + OFF_V;
    float* mq = smf + OFF_MQ;
    float* mk = smf + OFF_MK;

    const int bh = blockIdx.y;
    const int b  = bh >> 4;
    const int h  = bh & 15;
    const int r0 = blockIdx.x * FBM;

    const int tid  = threadIdx.x;
    const int wid  = tid >> 5;
    const int lane = tid & 31;
    const int ty4  = lane >> 2;
    const int tx4  = lane & 3;
    const int wm   = wid * 16;

    const float* Qg = g_q + (size_t)bh * NN * HD;
    const float* Kg = g_k + (size_t)bh * NN * HD;
    const float* Vg = g_v + (size_t)bh * NN * HD;

    // Load Q tile (tf32-rounded) + row mask
#pragma unroll
    for (int p = 0; p < 8; p++) {
        int fidx = p * 256 + tid;           // 2048 float4
        int r = fidx >> 4, c = (fidx & 15) * 4;
        float4 v = *(const float4*)&Qg[(size_t)(r0 + r) * HD + c];
        float* dst = &Qs[r * STR_A + c];
        dst[0] = to_tf32(v.x); dst[1] = to_tf32(v.y);
        dst[2] = to_tf32(v.z); dst[3] = to_tf32(v.w);
    }
    if (tid < FBM) mq[tid] = mask[b * NN + r0 + tid];
    __syncthreads();

    const float mqv_lo = mq[r0 ? (wm + ty4) : (wm + ty4)];  // same expr; keep simple
    const float mqv_hi = mq[wm + ty4 + 8];
    const float mq_lo = mq[wm + ty4];
    const float scale = 0.125f;   // 64^-0.5
    (void)mqv_lo;

    float o[8][4];
    float m_lo = -1e30f, m_hi = -1e30f, l_lo = 0.0f, l_hi = 0.0f;
#pragma unroll
    for (int ni = 0; ni < 8; ni++)
#pragma unroll
        for (int j = 0; j < 4; j++) o[ni][j] = 0.0f;

    for (int c0 = 0; c0 < NN; c0 += FBN) {
        // Load K, V tiles (tf32-rounded) + key mask
#pragma unroll
        for (int p = 0; p < 4; p++) {
            int fidx = p * 256 + tid;       // 1024 float4 each
            int r = fidx >> 4, c = (fidx & 15) * 4;
            float4 kv = *(const float4*)&Kg[(size_t)(c0 + r) * HD + c];
            float* dk = &Ks[r * STR_A + c];
            dk[0] = to_tf32(kv.x); dk[1] = to_tf32(kv.y);
            dk[2] = to_tf32(kv.z); dk[3] = to_tf32(kv.w);
            float4 vv = *(const float4*)&Vg[(size_t)(c0 + r) * HD + c];
            float* dv = &Vs[r * STR_V + c];
            dv[0] = to_tf32(vv.x); dv[1] = to_tf32(vv.y);
            dv[2] = to_tf32(vv.z); dv[3] = to_tf32(vv.w);
        }
        if (tid < FBN) mk[tid] = mask[b * NN + c0 + tid];
        __syncthreads();

        // ---- S = Q K^T (warp rows wm..wm+15, cols 0..63) ----
        float sA[8][4];
#pragma unroll
        for (int ni = 0; ni < 8; ni++)
#pragma unroll
            for (int j = 0; j < 4; j++) sA[ni][j] = 0.0f;

#pragma unroll
        for (int ks = 0; ks < 8; ks++) {
            const int k0 = ks * 8;
            uint32_t af[4];
            const int rq = (wm + ty4) * STR_A + k0 + tx4;
            af[0] = __float_as_uint(Qs[rq]);
            af[1] = __float_as_uint(Qs[rq + 8 * STR_A]);
            af[2] = __float_as_uint(Qs[rq + 4]);
            af[3] = __float_as_uint(Qs[rq + 8 * STR_A + 4]);
#pragma unroll
            for (int ni = 0; ni < 8; ni++) {
                const int rk = (ni * 8 + ty4) * STR_A + k0 + tx4;
                mma_tf32(sA[ni], af,
                         __float_as_uint(Ks[rk]),
                         __float_as_uint(Ks[rk + 4]));
            }
        }

        // ---- mask + online softmax ----
        float mx_lo = -1e30f, mx_hi = -1e30f;
#pragma unroll
        for (int ni = 0; ni < 8; ni++) {
            const float k0v = mk[ni * 8 + tx4 * 2];
            const float k1v = mk[ni * 8 + tx4 * 2 + 1];
            sA[ni][0] = sA[ni][0] * scale - mq_lo  * k0v;
            sA[ni][1] = sA[ni][1] * scale - mq_lo  * k1v;
            sA[ni][2] = sA[ni][2] * scale - mqv_hi * k0v;
            sA[ni][3] = sA[ni][3] * scale - mqv_hi * k1v;
            mx_lo = fmaxf(mx_lo, fmaxf(sA[ni][0], sA[ni][1]));
            mx_hi = fmaxf(mx_hi, fmaxf(sA[ni][2], sA[ni][3]));
        }
        mx_lo = fmaxf(mx_lo, __shfl_xor_sync(0xffffffffu, mx_lo, 1));
        mx_lo = fmaxf(mx_lo, __shfl_xor_sync(0xffffffffu, mx_lo, 2));
        mx_hi = fmaxf(mx_hi, __shfl_xor_sync(0xffffffffu, mx_hi, 1));
        mx_hi = fmaxf(mx_hi, __shfl_xor_sync(0xffffffffu, mx_hi, 2));

        const float mnew_lo = fmaxf(m_lo, mx_lo);
        const float mnew_hi = fmaxf(m_hi, mx_hi);
        const float fac_lo = __expf(m_lo - mnew_lo);
        const float fac_hi = __expf(m_hi - mnew_hi);

        float rs_lo = 0.0f, rs_hi = 0.0f;
#pragma unroll
        for (int ni = 0; ni < 8; ni++) {
            float p0 = to_tf32(__expf(sA[ni][0] - mnew_lo));
            float p1 = to_tf32(__expf(sA[ni][1] - mnew_lo));
            float p2 = to_tf32(__expf(sA[ni][2] - mnew_hi));
            float p3 = to_tf32(__expf(sA[ni][3] - mnew_hi));
            rs_lo += p0 + p1;
            rs_hi += p2 + p3;
            const int cbase = ni * 8 + tx4 * 2;
            *(float2*)&Ps[(wm + ty4)     * STR_A + cbase] = make_float2(p0, p1);
            *(float2*)&Ps[(wm + ty4 + 8) * STR_A + cbase] = make_float2(p2, p3);
        }
        rs_lo += __shfl_xor_sync(0xffffffffu, rs_lo, 1);
        rs_lo += __shfl_xor_sync(0xffffffffu, rs_lo, 2);
        rs_hi += __shfl_xor_sync(0xffffffffu, rs_hi, 1);
        rs_hi += __shfl_xor_sync(0xffffffffu, rs_hi, 2);

        l_lo = l_lo * fac_lo + rs_lo;  m_lo = mnew_lo;
        l_hi = l_hi * fac_hi + rs_hi;  m_hi = mnew_hi;
#pragma unroll
        for (int ni = 0; ni < 8; ni++) {
            o[ni][0] *= fac_lo; o[ni][1] *= fac_lo;
            o[ni][2] *= fac_hi; o[ni][3] *= fac_hi;
        }
        __syncwarp();   // P rows are warp-private; make lane writes visible

        // ---- O += P V ----
#pragma unroll
        for (int ks = 0; ks < 8; ks++) {
            const int k0 = ks * 8;
            uint32_t af[4];
            const int rp = (wm + ty4) * STR_A + k0 + tx4;
            af[0] = __float_as_uint(Ps[rp]);
            af[1] = __float_as_uint(Ps[rp + 8 * STR_A]);
            af[2] = __float_as_uint(Ps[rp + 4]);
            af[3] = __float_as_uint(Ps[rp + 8 * STR_A + 4]);
#pragma unroll
            for (int ni = 0; ni < 8; ni++) {
                const int rv = (k0 + tx4) * STR_V + ni * 8 + ty4;
                mma_tf32(o[ni], af,
                         __float_as_uint(Vs[rv]),
                         __float_as_uint(Vs[rv + 4 * STR_V]));
            }
        }
        __syncthreads();   // all warps done with Ks/Vs before next tile load
    }

    // Output: out[b][n][h*64+d]
    const float inv_lo = 1.0f / l_lo;
    const float inv_hi = 1.0f / l_hi;
    const int row = r0 + wm + ty4;
#pragma unroll
    for (int ni = 0; ni < 8; ni++) {
        const int col = h * HD + ni * 8 + tx4 * 2;
        *(float2*)&out[((size_t)(b * NN + row)) * CC + col] =
            make_float2(o[ni][0] * inv_lo, o[ni][1] * inv_lo);
        *(float2*)&out[((size_t)(b * NN + row + 8)) * CC + col] =
            make_float2(o[ni][2] * inv_hi, o[ni][3] * inv_hi);
    }
}

// ---------------------------------------------------------------------------
extern "C" void kernel_launch(void* const* d_in, const int* in_sizes, int n_in,
                              void* d_out, int out_size) {
    const float* inputs = (const float*)d_in[0];   // [B,N,C]
    const float* mask   = (const float*)d_in[1];   // [B,N]
    const float* W      = (const float*)d_in[2];   // [C,3C]
    float* out = (float*)d_out;                    // [B,N,C]

    cudaFuncSetAttribute((const void*)attn_mma_kernel,
                         cudaFuncAttributeMaxDynamicSharedMemorySize, FSM_BYTES);

    pe_add_kernel<<<(NN * CC + 255) / 256, 256>>>(inputs);
    wt_kernel<<<dim3(N3C / 32, K_TOT / 32), dim3(32, 8)>>>(W);
    qkv_mma_kernel<<<dim3(N3C / GBN, M_TOT / GBM), 256>>>();
    attn_mma_kernel<<<dim3(NN / FBM, BB * HH), 256, FSM_BYTES>>>(mask, out);
}

// round 4
// speedup vs baseline: 4.1637x; 1.2459x over previous
#include <cuda_runtime.h>
#include <math.h>
#include <stdint.h>

// Problem constants
#define BB 4
#define NN 2048
#define CC 1024
#define HH 16
#define HD 64
#define M_TOT (BB*NN)    // 8192
#define N3C   (3*CC)     // 3072
#define K_TOT CC         // 1024

// Scratch (static device globals — allocation-free per harness rules)
__device__ float g_x [M_TOT * CC];         // x = inputs + PE (tf32-rounded) [8192,1024]
__device__ float g_wt[N3C * CC];           // W^T (tf32-rounded)            [3072,1024]
__device__ float g_q[BB*HH*NN*HD];         // [B,H,N,hd] (tf32-rounded)
__device__ float g_k[BB*HH*NN*HD];
__device__ float g_v[BB*HH*NN*HD];

// ---------------------------------------------------------------------------
// Helpers
// ---------------------------------------------------------------------------
__device__ __forceinline__ float to_tf32(float v) {
    uint32_t r;
    asm("cvt.rna.tf32.f32 %0, %1;" : "=r"(r) : "f"(v));
    return __uint_as_float(r);
}

__device__ __forceinline__ void mma_tf32(float* c, const uint32_t* a,
                                         uint32_t b0, uint32_t b1) {
    asm volatile(
        "mma.sync.aligned.m16n8k8.row.col.f32.tf32.tf32.f32 "
        "{%0,%1,%2,%3}, {%4,%5,%6,%7}, {%8,%9}, {%0,%1,%2,%3};"
        : "+f"(c[0]), "+f"(c[1]), "+f"(c[2]), "+f"(c[3])
        : "r"(a[0]), "r"(a[1]), "r"(a[2]), "r"(a[3]), "r"(b0), "r"(b1));
}

__device__ __forceinline__ uint32_t smem_u32(const void* p) {
    uint32_t a;
    asm("{ .reg .u64 t; cvta.to.shared.u64 t, %1; cvt.u32.u64 %0, t; }"
        : "=r"(a) : "l"(p));
    return a;
}

#define CP_ASYNC16(dst, src) \
    asm volatile("cp.async.cg.shared.global [%0], [%1], 16;" \
        :: "r"(dst), "l"(src) : "memory")
#define CP_COMMIT() asm volatile("cp.async.commit_group;" ::: "memory")
#define CP_WAIT1()  asm volatile("cp.async.wait_group 1;" ::: "memory")

// ---------------------------------------------------------------------------
// Kernel 1: x = inputs + sinusoidal PE, rounded to tf32 (rna)
// ---------------------------------------------------------------------------
__global__ void pe_add_kernel(const float* __restrict__ in) {
    int idx = blockIdx.x * blockDim.x + threadIdx.x;
    if (idx >= NN * CC) return;
    int c = idx & (CC - 1);
    int n = idx >> 10;
    float e = (float)(2 * (c >> 1)) / (float)CC;
    float rate = powf(10000.0f, -e);
    float ang = (float)n * rate;
    float s, co;
    sincosf(ang, &s, &co);
    float pe = (c & 1) ? co : s;
#pragma unroll
    for (int b = 0; b < BB; b++) {
        g_x[b * (NN * CC) + idx] = to_tf32(in[b * (NN * CC) + idx] + pe);
    }
}

// ---------------------------------------------------------------------------
// Kernel 1b: W^T (tf32-rounded). W [1024,3072] -> g_wt [3072,1024]
// ---------------------------------------------------------------------------
__global__ __launch_bounds__(256) void wt_kernel(const float* __restrict__ W) {
    __shared__ float t[32][33];
    int tx = threadIdx.x, ty = threadIdx.y;
    int n0 = blockIdx.x * 32;
    int k0 = blockIdx.y * 32;
#pragma unroll
    for (int i = 0; i < 32; i += 8)
        t[ty + i][tx] = W[(size_t)(k0 + ty + i) * N3C + n0 + tx];
    __syncthreads();
#pragma unroll
    for (int i = 0; i < 32; i += 8)
        g_wt[(size_t)(n0 + ty + i) * K_TOT + k0 + tx] = to_tf32(t[tx][ty + i]);
}

// ---------------------------------------------------------------------------
// Kernel 2: QKV GEMM, mma.sync tf32, 3-stage cp.async pipeline.
// CTA 128x128, BK=16, 8 warps (2Mx4N, warp tile 64x32). Epilogue rounds to
// tf32 and scatters into Q/K/V [B,H,N,hd].
// ---------------------------------------------------------------------------
#define GBM 128
#define GBN 128
#define GBK 16
#define GSTR 20
#define GNKT (K_TOT / GBK)      // 64
#define QST  (256 * GSTR)       // floats per stage (A 128x20 + B 128x20)
#define QSM_BYTES (3 * QST * 4) // 61440

__global__ __launch_bounds__(256, 2) void qkv_mma_kernel() {
    extern __shared__ float qsm[];
    const uint32_t smb = smem_u32(qsm);

    const int tid  = threadIdx.x;
    const int wid  = tid >> 5;
    const int lane = tid & 31;
    const int ty4  = lane >> 2;
    const int tx4  = lane & 3;
    const int wm   = (wid & 1) * 64;
    const int wn   = (wid >> 1) * 32;
    const int row0 = blockIdx.y * GBM;
    const int col0 = blockIdx.x * GBN;

    const int ra = tid >> 2;
    const int c4 = (tid & 3) * 4;

    float acc[4][4][4];
#pragma unroll
    for (int mi = 0; mi < 4; mi++)
#pragma unroll
        for (int ni = 0; ni < 4; ni++)
#pragma unroll
            for (int j = 0; j < 4; j++) acc[mi][ni][j] = 0.0f;

    auto issue = [&](int s, int kt) {
        const int k0 = kt * GBK;
        const uint32_t dA = smb + (uint32_t)(s * QST) * 4;
        const uint32_t dB = dA + (uint32_t)(GBM * GSTR) * 4;
        CP_ASYNC16(dA + (uint32_t)(ra * GSTR + c4) * 4,
                   &g_x[(size_t)(row0 + ra) * K_TOT + k0 + c4]);
        CP_ASYNC16(dA + (uint32_t)((ra + 64) * GSTR + c4) * 4,
                   &g_x[(size_t)(row0 + ra + 64) * K_TOT + k0 + c4]);
        CP_ASYNC16(dB + (uint32_t)(ra * GSTR + c4) * 4,
                   &g_wt[(size_t)(col0 + ra) * K_TOT + k0 + c4]);
        CP_ASYNC16(dB + (uint32_t)((ra + 64) * GSTR + c4) * 4,
                   &g_wt[(size_t)(col0 + ra + 64) * K_TOT + k0 + c4]);
    };

    issue(0, 0); CP_COMMIT();
    issue(1, 1); CP_COMMIT();

    for (int kt = 0; kt < GNKT; kt++) {
        CP_WAIT1();
        __syncthreads();
        const float* As = qsm + (kt % 3) * QST;
        const float* Bs = As + GBM * GSTR;

#pragma unroll
        for (int ks = 0; ks < 2; ks++) {
            const int k0 = ks * 8;
            uint32_t af[4][4];
#pragma unroll
            for (int mi = 0; mi < 4; mi++) {
                const int r = (wm + mi * 16 + ty4) * GSTR + k0 + tx4;
                af[mi][0] = __float_as_uint(As[r]);
                af[mi][1] = __float_as_uint(As[r + 8 * GSTR]);
                af[mi][2] = __float_as_uint(As[r + 4]);
                af[mi][3] = __float_as_uint(As[r + 8 * GSTR + 4]);
            }
            uint32_t bf[4][2];
#pragma unroll
            for (int ni = 0; ni < 4; ni++) {
                const int cn = (wn + ni * 8 + ty4) * GSTR + k0 + tx4;
                bf[ni][0] = __float_as_uint(Bs[cn]);
                bf[ni][1] = __float_as_uint(Bs[cn + 4]);
            }
#pragma unroll
            for (int mi = 0; mi < 4; mi++)
#pragma unroll
                for (int ni = 0; ni < 4; ni++)
                    mma_tf32(acc[mi][ni], af[mi], bf[ni][0], bf[ni][1]);
        }
        __syncthreads();
        if (kt + 2 < GNKT) issue((kt + 2) % 3, kt + 2);
        CP_COMMIT();
    }

    // Epilogue: tf32-round + scatter to Q/K/V [B,H,N,hd]
#pragma unroll
    for (int mi = 0; mi < 4; mi++) {
        const int row = row0 + wm + mi * 16 + ty4;
        const int b = row >> 11;
        const int n = row & (NN - 1);
#pragma unroll
        for (int ni = 0; ni < 4; ni++) {
            const int col = col0 + wn + ni * 8 + tx4 * 2;
            const int t = col >> 10;
            const int h = (col >> 6) & 15;
            const int d = col & 63;
            float* base = (t == 0) ? g_q : ((t == 1) ? g_k : g_v);
            float* p0 = base + (((size_t)(b * HH + h)) * NN + n) * HD + d;
            ((float2*)p0)[0] = make_float2(to_tf32(acc[mi][ni][0]), to_tf32(acc[mi][ni][1]));
            float* p1 = base + (((size_t)(b * HH + h)) * NN + n + 8) * HD + d;
            ((float2*)p1)[0] = make_float2(to_tf32(acc[mi][ni][2]), to_tf32(acc[mi][ni][3]));
        }
    }
}

// ---------------------------------------------------------------------------
// Kernel 3: Flash attention, mma.sync tf32.
// CTA = (b,h, 128 query rows); 8 warps x 16 rows; key tiles of 64, double-
// buffered via cp.async (prefetch distance 1). P never touches smem: the
// S C-fragment is permuted to the PV A-fragment with quad shuffles.
// ---------------------------------------------------------------------------
#define FBM 128
#define FBN 64
#define FNT (NN / FBN)     // 32
#define STR_A 68
#define STR_V 72
// float offsets into dynamic smem
#define OFF_Q  0
#define OFF_K  (OFF_Q + FBM*STR_A)            // 8704
#define OFF_V  (OFF_K + 2*FBN*STR_A)          // 17408
#define OFF_MQ (OFF_V + 2*FBN*STR_V)          // 26624
#define OFF_MK (OFF_MQ + FBM)                 // 26752
#define FSM_FLOATS (OFF_MK + 2*FBN)           // 26880
#define FSM_BYTES  (FSM_FLOATS * 4)           // 107520

__global__ __launch_bounds__(256, 2) void attn_mma_kernel(const float* __restrict__ mask,
                                                          float* __restrict__ out) {
    extern __shared__ float smf[];
    const uint32_t smb = smem_u32(smf);
    const uint32_t sQ  = smb + OFF_Q * 4;
    const uint32_t sK  = smb + OFF_K * 4;
    const uint32_t sV  = smb + OFF_V * 4;
    const uint32_t sMQ = smb + OFF_MQ * 4;
    const uint32_t sMK = smb + OFF_MK * 4;

    float* Qs = smf + OFF_Q;
    float* Ks = smf + OFF_K;
    float* Vs = smf + OFF_V;
    float* mq = smf + OFF_MQ;
    float* mk = smf + OFF_MK;

    const int bh = blockIdx.y;
    const int b  = bh >> 4;
    const int h  = bh & 15;
    const int r0 = blockIdx.x * FBM;

    const int tid  = threadIdx.x;
    const int wid  = tid >> 5;
    const int lane = tid & 31;
    const int ty4  = lane >> 2;
    const int tx4  = lane & 3;
    const int wm   = wid * 16;

    const float* Qg = g_q + (size_t)bh * NN * HD;
    const float* Kg = g_k + (size_t)bh * NN * HD;
    const float* Vg = g_v + (size_t)bh * NN * HD;

    auto issue_kv = [&](int kt) {
        const int buf = kt & 1;
        const int c0 = kt * FBN;
#pragma unroll
        for (int p = 0; p < 4; p++) {
            int fidx = p * 256 + tid;
            int r = fidx >> 4, c = (fidx & 15) * 4;
            CP_ASYNC16(sK + (uint32_t)((buf * FBN + r) * STR_A + c) * 4,
                       Kg + (size_t)(c0 + r) * HD + c);
            CP_ASYNC16(sV + (uint32_t)((buf * FBN + r) * STR_V + c) * 4,
                       Vg + (size_t)(c0 + r) * HD + c);
        }
        if (tid < 16)
            CP_ASYNC16(sMK + (uint32_t)(buf * FBN + tid * 4) * 4,
                       mask + (size_t)b * NN + c0 + tid * 4);
    };

    // Prologue: Q tile + row mask, then KV tiles 0 and 1
    {
#pragma unroll
        for (int p = 0; p < 8; p++) {
            int fidx = p * 256 + tid;
            int r = fidx >> 4, c = (fidx & 15) * 4;
            CP_ASYNC16(sQ + (uint32_t)(r * STR_A + c) * 4,
                       Qg + (size_t)(r0 + r) * HD + c);
        }
        if (tid < 32)
            CP_ASYNC16(sMQ + (uint32_t)(tid * 4) * 4,
                       mask + (size_t)b * NN + r0 + tid * 4);
        CP_COMMIT();
        issue_kv(0); CP_COMMIT();
        issue_kv(1); CP_COMMIT();
    }

    float o[8][4];
    float m_lo = -1e30f, m_hi = -1e30f, l_lo = 0.0f, l_hi = 0.0f;
#pragma unroll
    for (int ni = 0; ni < 8; ni++)
#pragma unroll
        for (int j = 0; j < 4; j++) o[ni][j] = 0.0f;

    const float scale = 0.125f;   // 64^-0.5
    const uint32_t FULL = 0xffffffffu;
    const int srcA = (lane & ~3) | (tx4 >> 1);
    const int srcB = srcA + 2;
    const bool odd = (tx4 & 1) != 0;

    for (int kt = 0; kt < FNT; kt++) {
        CP_WAIT1();
        __syncthreads();
        const int kb = (kt & 1) * FBN;

        const float mq_lo = mq[wm + ty4];
        const float mq_hi = mq[wm + ty4 + 8];

        // ---- S = Q K^T ----
        float sA[8][4];
#pragma unroll
        for (int ni = 0; ni < 8; ni++)
#pragma unroll
            for (int j = 0; j < 4; j++) sA[ni][j] = 0.0f;

#pragma unroll
        for (int ks = 0; ks < 8; ks++) {
            const int k0 = ks * 8;
            uint32_t af[4];
            const int rq = (wm + ty4) * STR_A + k0 + tx4;
            af[0] = __float_as_uint(Qs[rq]);
            af[1] = __float_as_uint(Qs[rq + 8 * STR_A]);
            af[2] = __float_as_uint(Qs[rq + 4]);
            af[3] = __float_as_uint(Qs[rq + 8 * STR_A + 4]);
#pragma unroll
            for (int ni = 0; ni < 8; ni++) {
                const int rk = (kb + ni * 8 + ty4) * STR_A + k0 + tx4;
                mma_tf32(sA[ni], af,
                         __float_as_uint(Ks[rk]),
                         __float_as_uint(Ks[rk + 4]));
            }
        }

        // ---- mask + online softmax (P left in C-fragment registers) ----
        float mx_lo = -1e30f, mx_hi = -1e30f;
#pragma unroll
        for (int ni = 0; ni < 8; ni++) {
            const float k0v = mk[kb + ni * 8 + tx4 * 2];
            const float k1v = mk[kb + ni * 8 + tx4 * 2 + 1];
            sA[ni][0] = sA[ni][0] * scale - mq_lo * k0v;
            sA[ni][1] = sA[ni][1] * scale - mq_lo * k1v;
            sA[ni][2] = sA[ni][2] * scale - mq_hi * k0v;
            sA[ni][3] = sA[ni][3] * scale - mq_hi * k1v;
            mx_lo = fmaxf(mx_lo, fmaxf(sA[ni][0], sA[ni][1]));
            mx_hi = fmaxf(mx_hi, fmaxf(sA[ni][2], sA[ni][3]));
        }
        mx_lo = fmaxf(mx_lo, __shfl_xor_sync(FULL, mx_lo, 1));
        mx_lo = fmaxf(mx_lo, __shfl_xor_sync(FULL, mx_lo, 2));
        mx_hi = fmaxf(mx_hi, __shfl_xor_sync(FULL, mx_hi, 1));
        mx_hi = fmaxf(mx_hi, __shfl_xor_sync(FULL, mx_hi, 2));

        const float mnew_lo = fmaxf(m_lo, mx_lo);
        const float mnew_hi = fmaxf(m_hi, mx_hi);
        const float fac_lo = __expf(m_lo - mnew_lo);
        const float fac_hi = __expf(m_hi - mnew_hi);

        float rs_lo = 0.0f, rs_hi = 0.0f;
#pragma unroll
        for (int ni = 0; ni < 8; ni++) {
            sA[ni][0] = __expf(sA[ni][0] - mnew_lo);
            sA[ni][1] = __expf(sA[ni][1] - mnew_lo);
            sA[ni][2] = __expf(sA[ni][2] - mnew_hi);
            sA[ni][3] = __expf(sA[ni][3] - mnew_hi);
            rs_lo += sA[ni][0] + sA[ni][1];
            rs_hi += sA[ni][2] + sA[ni][3];
        }
        rs_lo += __shfl_xor_sync(FULL, rs_lo, 1);
        rs_lo += __shfl_xor_sync(FULL, rs_lo, 2);
        rs_hi += __shfl_xor_sync(FULL, rs_hi, 1);
        rs_hi += __shfl_xor_sync(FULL, rs_hi, 2);

        l_lo = l_lo * fac_lo + rs_lo;  m_lo = mnew_lo;
        l_hi = l_hi * fac_hi + rs_hi;  m_hi = mnew_hi;
#pragma unroll
        for (int ni = 0; ni < 8; ni++) {
            o[ni][0] *= fac_lo; o[ni][1] *= fac_lo;
            o[ni][2] *= fac_hi; o[ni][3] *= fac_hi;
        }

        // ---- O += P V : A-fragment built from C-fragment via quad shuffles ----
#pragma unroll
        for (int ks = 0; ks < 8; ks++) {
            const float x0 = __shfl_sync(FULL, sA[ks][0], srcA);
            const float x1 = __shfl_sync(FULL, sA[ks][1], srcA);
            const float x2 = __shfl_sync(FULL, sA[ks][2], srcA);
            const float x3 = __shfl_sync(FULL, sA[ks][3], srcA);
            const float y0 = __shfl_sync(FULL, sA[ks][0], srcB);
            const float y1 = __shfl_sync(FULL, sA[ks][1], srcB);
            const float y2 = __shfl_sync(FULL, sA[ks][2], srcB);
            const float y3 = __shfl_sync(FULL, sA[ks][3], srcB);
            uint32_t af[4];
            af[0] = __float_as_uint(odd ? x1 : x0);   // (row lo, key tx4)
            af[1] = __float_as_uint(odd ? x3 : x2);   // (row hi, key tx4)
            af[2] = __float_as_uint(odd ? y1 : y0);   // (row lo, key tx4+4)
            af[3] = __float_as_uint(odd ? y3 : y2);   // (row hi, key tx4+4)
            const int k0 = ks * 8;
#pragma unroll
            for (int ni = 0; ni < 8; ni++) {
                const int rv = (kb + k0 + tx4) * STR_V + ni * 8 + ty4;
                mma_tf32(o[ni], af,
                         __float_as_uint(Vs[rv]),
                         __float_as_uint(Vs[rv + 4 * STR_V]));
            }
        }

        __syncthreads();
        if (kt + 2 < FNT) issue_kv(kt + 2);
        CP_COMMIT();
    }

    // Output: out[b][n][h*64+d]
    const float inv_lo = 1.0f / l_lo;
    const float inv_hi = 1.0f / l_hi;
    const int row = r0 + wm + ty4;
#pragma unroll
    for (int ni = 0; ni < 8; ni++) {
        const int col = h * HD + ni * 8 + tx4 * 2;
        *(float2*)&out[((size_t)(b * NN + row)) * CC + col] =
            make_float2(o[ni][0] * inv_lo, o[ni][1] * inv_lo);
        *(float2*)&out[((size_t)(b * NN + row + 8)) * CC + col] =
            make_float2(o[ni][2] * inv_hi, o[ni][3] * inv_hi);
    }
}

// ---------------------------------------------------------------------------
extern "C" void kernel_launch(void* const* d_in, const int* in_sizes, int n_in,
                              void* d_out, int out_size) {
    const float* inputs = (const float*)d_in[0];   // [B,N,C]
    const float* mask   = (const float*)d_in[1];   // [B,N]
    const float* W      = (const float*)d_in[2];   // [C,3C]
    float* out = (float*)d_out;                    // [B,N,C]

    cudaFuncSetAttribute((const void*)qkv_mma_kernel,
                         cudaFuncAttributeMaxDynamicSharedMemorySize, QSM_BYTES);
    cudaFuncSetAttribute((const void*)attn_mma_kernel,
                         cudaFuncAttributeMaxDynamicSharedMemorySize, FSM_BYTES);

    pe_add_kernel<<<(NN * CC + 255) / 256, 256>>>(inputs);
    wt_kernel<<<dim3(N3C / 32, K_TOT / 32), dim3(32, 8)>>>(W);
    qkv_mma_kernel<<<dim3(N3C / GBN, M_TOT / GBM), 256, QSM_BYTES>>>();
    attn_mma_kernel<<<dim3(NN / FBM, BB * HH), 256, FSM_BYTES>>>(mask, out);
}

// round 5
// speedup vs baseline: 4.5459x; 1.0918x over previous
#include <cuda_runtime.h>
#include <math.h>
#include <stdint.h>

// Problem constants
#define BB 4
#define NN 2048
#define CC 1024
#define HH 16
#define HD 64
#define M_TOT (BB*NN)    // 8192
#define N3C   (3*CC)     // 3072
#define K_TOT CC         // 1024

// Scratch (static device globals — allocation-free per harness rules)
__device__ float g_x [M_TOT * CC];         // x = inputs + PE (tf32-rounded) [8192,1024]
__device__ float g_wt[N3C * CC];           // W^T (tf32-rounded)            [3072,1024]
__device__ float g_q[BB*HH*NN*HD];         // [B,H,N,hd] (tf32-rounded)
__device__ float g_k[BB*HH*NN*HD];
__device__ float g_v[BB*HH*NN*HD];

// ---------------------------------------------------------------------------
// Helpers
// ---------------------------------------------------------------------------
__device__ __forceinline__ float to_tf32(float v) {
    uint32_t r;
    asm("cvt.rna.tf32.f32 %0, %1;" : "=r"(r) : "f"(v));
    return __uint_as_float(r);
}

__device__ __forceinline__ void mma_tf32(float* c, const uint32_t* a,
                                         uint32_t b0, uint32_t b1) {
    asm volatile(
        "mma.sync.aligned.m16n8k8.row.col.f32.tf32.tf32.f32 "
        "{%0,%1,%2,%3}, {%4,%5,%6,%7}, {%8,%9}, {%0,%1,%2,%3};"
        : "+f"(c[0]), "+f"(c[1]), "+f"(c[2]), "+f"(c[3])
        : "r"(a[0]), "r"(a[1]), "r"(a[2]), "r"(a[3]), "r"(b0), "r"(b1));
}

__device__ __forceinline__ uint32_t smem_u32(const void* p) {
    uint32_t a;
    asm("{ .reg .u64 t; cvta.to.shared.u64 t, %1; cvt.u32.u64 %0, t; }"
        : "=r"(a) : "l"(p));
    return a;
}

#define CP_ASYNC16(dst, src) \
    asm volatile("cp.async.cg.shared.global [%0], [%1], 16;" \
        :: "r"(dst), "l"(src) : "memory")
#define CP_COMMIT() asm volatile("cp.async.commit_group;" ::: "memory")
#define CP_WAIT1()  asm volatile("cp.async.wait_group 1;" ::: "memory")

// ---------------------------------------------------------------------------
// Kernel 1: x = inputs + sinusoidal PE, rounded to tf32 (rna)
// ---------------------------------------------------------------------------
__global__ void pe_add_kernel(const float* __restrict__ in) {
    int idx = blockIdx.x * blockDim.x + threadIdx.x;
    if (idx >= NN * CC) return;
    int c = idx & (CC - 1);
    int n = idx >> 10;
    float e = (float)(2 * (c >> 1)) / (float)CC;
    float rate = powf(10000.0f, -e);
    float ang = (float)n * rate;
    float s, co;
    sincosf(ang, &s, &co);
    float pe = (c & 1) ? co : s;
#pragma unroll
    for (int b = 0; b < BB; b++) {
        g_x[b * (NN * CC) + idx] = to_tf32(in[b * (NN * CC) + idx] + pe);
    }
}

// ---------------------------------------------------------------------------
// Kernel 1b: W^T (tf32-rounded). W [1024,3072] -> g_wt [3072,1024]
// ---------------------------------------------------------------------------
__global__ __launch_bounds__(256) void wt_kernel(const float* __restrict__ W) {
    __shared__ float t[32][33];
    int tx = threadIdx.x, ty = threadIdx.y;
    int n0 = blockIdx.x * 32;
    int k0 = blockIdx.y * 32;
#pragma unroll
    for (int i = 0; i < 32; i += 8)
        t[ty + i][tx] = W[(size_t)(k0 + ty + i) * N3C + n0 + tx];
    __syncthreads();
#pragma unroll
    for (int i = 0; i < 32; i += 8)
        g_wt[(size_t)(n0 + ty + i) * K_TOT + k0 + tx] = to_tf32(t[tx][ty + i]);
}

// ---------------------------------------------------------------------------
// Kernel 2: QKV GEMM, mma.sync tf32, 3-stage cp.async pipeline. (unchanged)
// ---------------------------------------------------------------------------
#define GBM 128
#define GBN 128
#define GBK 16
#define GSTR 20
#define GNKT (K_TOT / GBK)      // 64
#define QST  (256 * GSTR)
#define QSM_BYTES (3 * QST * 4) // 61440

__global__ __launch_bounds__(256, 2) void qkv_mma_kernel() {
    extern __shared__ float qsm[];
    const uint32_t smb = smem_u32(qsm);

    const int tid  = threadIdx.x;
    const int wid  = tid >> 5;
    const int lane = tid & 31;
    const int ty4  = lane >> 2;
    const int tx4  = lane & 3;
    const int wm   = (wid & 1) * 64;
    const int wn   = (wid >> 1) * 32;
    const int row0 = blockIdx.y * GBM;
    const int col0 = blockIdx.x * GBN;

    const int ra = tid >> 2;
    const int c4 = (tid & 3) * 4;

    float acc[4][4][4];
#pragma unroll
    for (int mi = 0; mi < 4; mi++)
#pragma unroll
        for (int ni = 0; ni < 4; ni++)
#pragma unroll
            for (int j = 0; j < 4; j++) acc[mi][ni][j] = 0.0f;

    auto issue = [&](int s, int kt) {
        const int k0 = kt * GBK;
        const uint32_t dA = smb + (uint32_t)(s * QST) * 4;
        const uint32_t dB = dA + (uint32_t)(GBM * GSTR) * 4;
        CP_ASYNC16(dA + (uint32_t)(ra * GSTR + c4) * 4,
                   &g_x[(size_t)(row0 + ra) * K_TOT + k0 + c4]);
        CP_ASYNC16(dA + (uint32_t)((ra + 64) * GSTR + c4) * 4,
                   &g_x[(size_t)(row0 + ra + 64) * K_TOT + k0 + c4]);
        CP_ASYNC16(dB + (uint32_t)(ra * GSTR + c4) * 4,
                   &g_wt[(size_t)(col0 + ra) * K_TOT + k0 + c4]);
        CP_ASYNC16(dB + (uint32_t)((ra + 64) * GSTR + c4) * 4,
                   &g_wt[(size_t)(col0 + ra + 64) * K_TOT + k0 + c4]);
    };

    issue(0, 0); CP_COMMIT();
    issue(1, 1); CP_COMMIT();

    for (int kt = 0; kt < GNKT; kt++) {
        CP_WAIT1();
        __syncthreads();
        const float* As = qsm + (kt % 3) * QST;
        const float* Bs = As + GBM * GSTR;

#pragma unroll
        for (int ks = 0; ks < 2; ks++) {
            const int k0 = ks * 8;
            uint32_t af[4][4];
#pragma unroll
            for (int mi = 0; mi < 4; mi++) {
                const int r = (wm + mi * 16 + ty4) * GSTR + k0 + tx4;
                af[mi][0] = __float_as_uint(As[r]);
                af[mi][1] = __float_as_uint(As[r + 8 * GSTR]);
                af[mi][2] = __float_as_uint(As[r + 4]);
                af[mi][3] = __float_as_uint(As[r + 8 * GSTR + 4]);
            }
            uint32_t bf[4][2];
#pragma unroll
            for (int ni = 0; ni < 4; ni++) {
                const int cn = (wn + ni * 8 + ty4) * GSTR + k0 + tx4;
                bf[ni][0] = __float_as_uint(Bs[cn]);
                bf[ni][1] = __float_as_uint(Bs[cn + 4]);
            }
#pragma unroll
            for (int mi = 0; mi < 4; mi++)
#pragma unroll
                for (int ni = 0; ni < 4; ni++)
                    mma_tf32(acc[mi][ni], af[mi], bf[ni][0], bf[ni][1]);
        }
        __syncthreads();
        if (kt + 2 < GNKT) issue((kt + 2) % 3, kt + 2);
        CP_COMMIT();
    }

#pragma unroll
    for (int mi = 0; mi < 4; mi++) {
        const int row = row0 + wm + mi * 16 + ty4;
        const int b = row >> 11;
        const int n = row & (NN - 1);
#pragma unroll
        for (int ni = 0; ni < 4; ni++) {
            const int col = col0 + wn + ni * 8 + tx4 * 2;
            const int t = col >> 10;
            const int h = (col >> 6) & 15;
            const int d = col & 63;
            float* base = (t == 0) ? g_q : ((t == 1) ? g_k : g_v);
            float* p0 = base + (((size_t)(b * HH + h)) * NN + n) * HD + d;
            ((float2*)p0)[0] = make_float2(to_tf32(acc[mi][ni][0]), to_tf32(acc[mi][ni][1]));
            float* p1 = base + (((size_t)(b * HH + h)) * NN + n + 8) * HD + d;
            ((float2*)p1)[0] = make_float2(to_tf32(acc[mi][ni][2]), to_tf32(acc[mi][ni][3]));
        }
    }
}

// ---------------------------------------------------------------------------
// Kernel 3: Flash attention, mma.sync tf32.
// CTA = (b,h, 128 query rows); 4 warps x 32 rows (two m16 tiles per warp) so
// every K/V fragment load feeds 2 MMAs (LDS/MMA: S 2.5->1.5, PV 2->1).
// Key tiles of 64, double-buffered via cp.async; P stays in registers
// (quad-shuffle C->A fragment permutation).
// ---------------------------------------------------------------------------
#define FBM 128
#define FBN 64
#define FNT (NN / FBN)     // 32
#define STR_A 68
#define STR_V 72
#define OFF_Q  0
#define OFF_K  (OFF_Q + FBM*STR_A)            // 8704
#define OFF_V  (OFF_K + 2*FBN*STR_A)          // 17408
#define OFF_MQ (OFF_V + 2*FBN*STR_V)          // 26624
#define OFF_MK (OFF_MQ + FBM)                 // 26752
#define FSM_FLOATS (OFF_MK + 2*FBN)           // 26880
#define FSM_BYTES  (FSM_FLOATS * 4)           // 107520

__global__ __launch_bounds__(128, 2) void attn_mma_kernel(const float* __restrict__ mask,
                                                          float* __restrict__ out) {
    extern __shared__ float smf[];
    const uint32_t smb = smem_u32(smf);
    const uint32_t sQ  = smb + OFF_Q * 4;
    const uint32_t sK  = smb + OFF_K * 4;
    const uint32_t sV  = smb + OFF_V * 4;
    const uint32_t sMQ = smb + OFF_MQ * 4;
    const uint32_t sMK = smb + OFF_MK * 4;

    float* Qs = smf + OFF_Q;
    float* Ks = smf + OFF_K;
    float* Vs = smf + OFF_V;
    float* mq = smf + OFF_MQ;
    float* mk = smf + OFF_MK;

    const int bh = blockIdx.y;
    const int b  = bh >> 4;
    const int h  = bh & 15;
    const int r0 = blockIdx.x * FBM;

    const int tid  = threadIdx.x;
    const int wid  = tid >> 5;
    const int lane = tid & 31;
    const int ty4  = lane >> 2;
    const int tx4  = lane & 3;
    const int wm   = wid * 32;    // 4 warps x 32 rows

    const float* Qg = g_q + (size_t)bh * NN * HD;
    const float* Kg = g_k + (size_t)bh * NN * HD;
    const float* Vg = g_v + (size_t)bh * NN * HD;

    auto issue_kv = [&](int kt) {
        const int buf = kt & 1;
        const int c0 = kt * FBN;
#pragma unroll
        for (int p = 0; p < 8; p++) {
            int fidx = p * 128 + tid;          // 1024 float4 each
            int r = fidx >> 4, c = (fidx & 15) * 4;
            CP_ASYNC16(sK + (uint32_t)((buf * FBN + r) * STR_A + c) * 4,
                       Kg + (size_t)(c0 + r) * HD + c);
            CP_ASYNC16(sV + (uint32_t)((buf * FBN + r) * STR_V + c) * 4,
                       Vg + (size_t)(c0 + r) * HD + c);
        }
        if (tid < 16)
            CP_ASYNC16(sMK + (uint32_t)(buf * FBN + tid * 4) * 4,
                       mask + (size_t)b * NN + c0 + tid * 4);
    };

    // Prologue: Q tile + row mask, then KV tiles 0 and 1
    {
#pragma unroll
        for (int p = 0; p < 16; p++) {
            int fidx = p * 128 + tid;          // 2048 float4
            int r = fidx >> 4, c = (fidx & 15) * 4;
            CP_ASYNC16(sQ + (uint32_t)(r * STR_A + c) * 4,
                       Qg + (size_t)(r0 + r) * HD + c);
        }
        if (tid < 32)
            CP_ASYNC16(sMQ + (uint32_t)(tid * 4) * 4,
                       mask + (size_t)b * NN + r0 + tid * 4);
        CP_COMMIT();
        issue_kv(0); CP_COMMIT();
        issue_kv(1); CP_COMMIT();
    }

    float o[2][8][4];
    float m_lo[2], m_hi[2], l_lo[2], l_hi[2];
#pragma unroll
    for (int mi = 0; mi < 2; mi++) {
        m_lo[mi] = -1e30f; m_hi[mi] = -1e30f;
        l_lo[mi] = 0.0f;   l_hi[mi] = 0.0f;
#pragma unroll
        for (int ni = 0; ni < 8; ni++)
#pragma unroll
            for (int j = 0; j < 4; j++) o[mi][ni][j] = 0.0f;
    }

    const float scale = 0.125f;   // 64^-0.5
    const uint32_t FULL = 0xffffffffu;
    const int srcA = (lane & ~3) | (tx4 >> 1);
    const int srcB = srcA + 2;
    const bool odd = (tx4 & 1) != 0;

    for (int kt = 0; kt < FNT; kt++) {
        CP_WAIT1();
        __syncthreads();
        const int kb = (kt & 1) * FBN;

        // ---- S = Q K^T : sA[mi][ni] for rows wm+mi*16+ty4(+8) ----
        float sA[2][8][4];
#pragma unroll
        for (int mi = 0; mi < 2; mi++)
#pragma unroll
            for (int ni = 0; ni < 8; ni++)
#pragma unroll
                for (int j = 0; j < 4; j++) sA[mi][ni][j] = 0.0f;

#pragma unroll
        for (int ks = 0; ks < 8; ks++) {
            const int k0 = ks * 8;
            uint32_t af[2][4];
#pragma unroll
            for (int mi = 0; mi < 2; mi++) {
                const int rq = (wm + mi * 16 + ty4) * STR_A + k0 + tx4;
                af[mi][0] = __float_as_uint(Qs[rq]);
                af[mi][1] = __float_as_uint(Qs[rq + 8 * STR_A]);
                af[mi][2] = __float_as_uint(Qs[rq + 4]);
                af[mi][3] = __float_as_uint(Qs[rq + 8 * STR_A + 4]);
            }
#pragma unroll
            for (int ni = 0; ni < 8; ni++) {
                const int rk = (kb + ni * 8 + ty4) * STR_A + k0 + tx4;
                const uint32_t b0 = __float_as_uint(Ks[rk]);
                const uint32_t b1 = __float_as_uint(Ks[rk + 4]);
                mma_tf32(sA[0][ni], af[0], b0, b1);
                mma_tf32(sA[1][ni], af[1], b0, b1);
            }
        }

        // ---- mask + online softmax per mi ----
#pragma unroll
        for (int mi = 0; mi < 2; mi++) {
            const float mq_l = mq[wm + mi * 16 + ty4];
            const float mq_h = mq[wm + mi * 16 + ty4 + 8];
            float mx_lo = -1e30f, mx_hi = -1e30f;
#pragma unroll
            for (int ni = 0; ni < 8; ni++) {
                const float k0v = mk[kb + ni * 8 + tx4 * 2];
                const float k1v = mk[kb + ni * 8 + tx4 * 2 + 1];
                sA[mi][ni][0] = sA[mi][ni][0] * scale - mq_l * k0v;
                sA[mi][ni][1] = sA[mi][ni][1] * scale - mq_l * k1v;
                sA[mi][ni][2] = sA[mi][ni][2] * scale - mq_h * k0v;
                sA[mi][ni][3] = sA[mi][ni][3] * scale - mq_h * k1v;
                mx_lo = fmaxf(mx_lo, fmaxf(sA[mi][ni][0], sA[mi][ni][1]));
                mx_hi = fmaxf(mx_hi, fmaxf(sA[mi][ni][2], sA[mi][ni][3]));
            }
            mx_lo = fmaxf(mx_lo, __shfl_xor_sync(FULL, mx_lo, 1));
            mx_lo = fmaxf(mx_lo, __shfl_xor_sync(FULL, mx_lo, 2));
            mx_hi = fmaxf(mx_hi, __shfl_xor_sync(FULL, mx_hi, 1));
            mx_hi = fmaxf(mx_hi, __shfl_xor_sync(FULL, mx_hi, 2));

            const float mnew_lo = fmaxf(m_lo[mi], mx_lo);
            const float mnew_hi = fmaxf(m_hi[mi], mx_hi);
            const float fac_lo = __expf(m_lo[mi] - mnew_lo);
            const float fac_hi = __expf(m_hi[mi] - mnew_hi);

            float rs_lo = 0.0f, rs_hi = 0.0f;
#pragma unroll
            for (int ni = 0; ni < 8; ni++) {
                sA[mi][ni][0] = __expf(sA[mi][ni][0] - mnew_lo);
                sA[mi][ni][1] = __expf(sA[mi][ni][1] - mnew_lo);
                sA[mi][ni][2] = __expf(sA[mi][ni][2] - mnew_hi);
                sA[mi][ni][3] = __expf(sA[mi][ni][3] - mnew_hi);
                rs_lo += sA[mi][ni][0] + sA[mi][ni][1];
                rs_hi += sA[mi][ni][2] + sA[mi][ni][3];
            }
            rs_lo += __shfl_xor_sync(FULL, rs_lo, 1);
            rs_lo += __shfl_xor_sync(FULL, rs_lo, 2);
            rs_hi += __shfl_xor_sync(FULL, rs_hi, 1);
            rs_hi += __shfl_xor_sync(FULL, rs_hi, 2);

            l_lo[mi] = l_lo[mi] * fac_lo + rs_lo;  m_lo[mi] = mnew_lo;
            l_hi[mi] = l_hi[mi] * fac_hi + rs_hi;  m_hi[mi] = mnew_hi;
#pragma unroll
            for (int ni = 0; ni < 8; ni++) {
                o[mi][ni][0] *= fac_lo; o[mi][ni][1] *= fac_lo;
                o[mi][ni][2] *= fac_hi; o[mi][ni][3] *= fac_hi;
            }
        }

        // ---- O += P V : A-fragments via quad shuffles; V fragment reused 2x ----
#pragma unroll
        for (int ks = 0; ks < 8; ks++) {
            uint32_t af[2][4];
#pragma unroll
            for (int mi = 0; mi < 2; mi++) {
                const float x0 = __shfl_sync(FULL, sA[mi][ks][0], srcA);
                const float x1 = __shfl_sync(FULL, sA[mi][ks][1], srcA);
                const float x2 = __shfl_sync(FULL, sA[mi][ks][2], srcA);
                const float x3 = __shfl_sync(FULL, sA[mi][ks][3], srcA);
                const float y0 = __shfl_sync(FULL, sA[mi][ks][0], srcB);
                const float y1 = __shfl_sync(FULL, sA[mi][ks][1], srcB);
                const float y2 = __shfl_sync(FULL, sA[mi][ks][2], srcB);
                const float y3 = __shfl_sync(FULL, sA[mi][ks][3], srcB);
                af[mi][0] = __float_as_uint(odd ? x1 : x0);
                af[mi][1] = __float_as_uint(odd ? x3 : x2);
                af[mi][2] = __float_as_uint(odd ? y1 : y0);
                af[mi][3] = __float_as_uint(odd ? y3 : y2);
            }
            const int k0 = ks * 8;
#pragma unroll
            for (int ni = 0; ni < 8; ni++) {
                const int rv = (kb + k0 + tx4) * STR_V + ni * 8 + ty4;
                const uint32_t b0 = __float_as_uint(Vs[rv]);
                const uint32_t b1 = __float_as_uint(Vs[rv + 4 * STR_V]);
                mma_tf32(o[0][ni], af[0], b0, b1);
                mma_tf32(o[1][ni], af[1], b0, b1);
            }
        }

        __syncthreads();
        if (kt + 2 < FNT) issue_kv(kt + 2);
        CP_COMMIT();
    }

    // Output: out[b][n][h*64+d]
#pragma unroll
    for (int mi = 0; mi < 2; mi++) {
        const float inv_lo = 1.0f / l_lo[mi];
        const float inv_hi = 1.0f / l_hi[mi];
        const int row = r0 + wm + mi * 16 + ty4;
#pragma unroll
        for (int ni = 0; ni < 8; ni++) {
            const int col = h * HD + ni * 8 + tx4 * 2;
            *(float2*)&out[((size_t)(b * NN + row)) * CC + col] =
                make_float2(o[mi][ni][0] * inv_lo, o[mi][ni][1] * inv_lo);
            *(float2*)&out[((size_t)(b * NN + row + 8)) * CC + col] =
                make_float2(o[mi][ni][2] * inv_hi, o[mi][ni][3] * inv_hi);
        }
    }
}

// ---------------------------------------------------------------------------
extern "C" void kernel_launch(void* const* d_in, const int* in_sizes, int n_in,
                              void* d_out, int out_size) {
    const float* inputs = (const float*)d_in[0];   // [B,N,C]
    const float* mask   = (const float*)d_in[1];   // [B,N]
    const float* W      = (const float*)d_in[2];   // [C,3C]
    float* out = (float*)d_out;                    // [B,N,C]

    cudaFuncSetAttribute((const void*)qkv_mma_kernel,
                         cudaFuncAttributeMaxDynamicSharedMemorySize, QSM_BYTES);
    cudaFuncSetAttribute((const void*)attn_mma_kernel,
                         cudaFuncAttributeMaxDynamicSharedMemorySize, FSM_BYTES);

    pe_add_kernel<<<(NN * CC + 255) / 256, 256>>>(inputs);
    wt_kernel<<<dim3(N3C / 32, K_TOT / 32), dim3(32, 8)>>>(W);
    qkv_mma_kernel<<<dim3(N3C / GBN, M_TOT / GBM), 256, QSM_BYTES>>>();
    attn_mma_kernel<<<dim3(NN / FBM, BB * HH), 128, FSM_BYTES>>>(mask, out);
}

// round 6
// speedup vs baseline: 7.9727x; 1.7538x over previous
#include <cuda_runtime.h>
#include <cuda_fp16.h>
#include <math.h>
#include <stdint.h>

// Problem constants
#define BB 4
#define NN 2048
#define CC 1024
#define HH 16
#define HD 64
#define M_TOT (BB*NN)    // 8192
#define N3C   (3*CC)     // 3072
#define K_TOT CC         // 1024

// Scratch (static device globals — allocation-free per harness rules)
__device__ __half g_x [M_TOT * CC];        // x = inputs + PE (fp16)  [8192,1024]
__device__ __half g_wt[N3C * CC];          // W^T (fp16)              [3072,1024]
__device__ __half g_q [BB*HH*NN*HD];       // [B,H,N,hd]
__device__ __half g_k [BB*HH*NN*HD];       // [B,H,N,hd]
__device__ __half g_vt[BB*HH*HD*NN];       // V transposed: [B,H,hd,N]

// ---------------------------------------------------------------------------
// Helpers
// ---------------------------------------------------------------------------
__device__ __forceinline__ void mma_f16(float* c, const uint32_t* a,
                                        uint32_t b0, uint32_t b1) {
    asm volatile(
        "mma.sync.aligned.m16n8k16.row.col.f32.f16.f16.f32 "
        "{%0,%1,%2,%3}, {%4,%5,%6,%7}, {%8,%9}, {%0,%1,%2,%3};"
        : "+f"(c[0]), "+f"(c[1]), "+f"(c[2]), "+f"(c[3])
        : "r"(a[0]), "r"(a[1]), "r"(a[2]), "r"(a[3]), "r"(b0), "r"(b1));
}

__device__ __forceinline__ uint32_t f2h2(float lo, float hi) {
    __half2 h = __floats2half2_rn(lo, hi);
    return *(uint32_t*)&h;
}

__device__ __forceinline__ uint32_t smem_u32(const void* p) {
    uint32_t a;
    asm("{ .reg .u64 t; cvta.to.shared.u64 t, %1; cvt.u32.u64 %0, t; }"
        : "=r"(a) : "l"(p));
    return a;
}

#define CP_ASYNC16(dst, src) \
    asm volatile("cp.async.cg.shared.global [%0], [%1], 16;" \
        :: "r"(dst), "l"(src) : "memory")
#define CP_COMMIT() asm volatile("cp.async.commit_group;" ::: "memory")
#define CP_WAIT1()  asm volatile("cp.async.wait_group 1;" ::: "memory")

// ---------------------------------------------------------------------------
// Kernel 1: x = inputs + sinusoidal PE -> fp16
// ---------------------------------------------------------------------------
__global__ void pe_add_kernel(const float* __restrict__ in) {
    int idx = blockIdx.x * blockDim.x + threadIdx.x;
    if (idx >= NN * CC) return;
    int c = idx & (CC - 1);
    int n = idx >> 10;
    float e = (float)(2 * (c >> 1)) / (float)CC;
    float rate = powf(10000.0f, -e);
    float ang = (float)n * rate;
    float s, co;
    sincosf(ang, &s, &co);
    float pe = (c & 1) ? co : s;
#pragma unroll
    for (int b = 0; b < BB; b++) {
        g_x[b * (NN * CC) + idx] = __float2half_rn(in[b * (NN * CC) + idx] + pe);
    }
}

// ---------------------------------------------------------------------------
// Kernel 1b: W^T -> fp16. W [1024,3072] -> g_wt [3072,1024]
// ---------------------------------------------------------------------------
__global__ __launch_bounds__(256) void wt_kernel(const float* __restrict__ W) {
    __shared__ float t[32][33];
    int tx = threadIdx.x, ty = threadIdx.y;
    int n0 = blockIdx.x * 32;
    int k0 = blockIdx.y * 32;
#pragma unroll
    for (int i = 0; i < 32; i += 8)
        t[ty + i][tx] = W[(size_t)(k0 + ty + i) * N3C + n0 + tx];
    __syncthreads();
#pragma unroll
    for (int i = 0; i < 32; i += 8)
        g_wt[(size_t)(n0 + ty + i) * K_TOT + k0 + tx] = __float2half_rn(t[tx][ty + i]);
}

// ---------------------------------------------------------------------------
// Kernel 2: QKV GEMM, mma.sync fp16 (m16n8k16), 3-stage cp.async pipeline.
// CTA 128x128, BK=32, 8 warps (2Mx4N, warp tile 64x32). Epilogue writes fp16
// Q/K [B,H,N,hd] and V transposed [B,H,hd,N].
// ---------------------------------------------------------------------------
#define GBM 128
#define GBN 128
#define GBK 32
#define GSTRH 40                 // halves per row (80B, conflict-free)
#define GNKT (K_TOT / GBK)       // 32
#define QSTH (GBM * GSTRH)       // halves per tile per stage (5120)
#define QSM_BYTES (3 * 2 * QSTH * 2)   // 61440

__global__ __launch_bounds__(256, 2) void qkv_mma_kernel() {
    extern __shared__ char qsm[];
    const uint32_t smb = smem_u32(qsm);
    __half* smh = (__half*)qsm;

    const int tid  = threadIdx.x;
    const int wid  = tid >> 5;
    const int lane = tid & 31;
    const int g    = lane >> 2;    // 0..7
    const int t    = lane & 3;     // 0..3
    const int wm   = (wid & 1) * 64;
    const int wn   = (wid >> 1) * 32;
    const int row0 = blockIdx.y * GBM;
    const int col0 = blockIdx.x * GBN;

    float acc[4][4][4];
#pragma unroll
    for (int mi = 0; mi < 4; mi++)
#pragma unroll
        for (int ni = 0; ni < 4; ni++)
#pragma unroll
            for (int j = 0; j < 4; j++) acc[mi][ni][j] = 0.0f;

    auto issue = [&](int s, int kt) {
        const int k0 = kt * GBK;
        const uint32_t dA = smb + (uint32_t)(s * 2 * QSTH) * 2;
        const uint32_t dB = dA + (uint32_t)QSTH * 2;
#pragma unroll
        for (int p = 0; p < 2; p++) {
            int idx = p * 256 + tid;            // 512 chunks per tile
            int row = idx >> 2, ch = (idx & 3) * 8;
            CP_ASYNC16(dA + (uint32_t)(row * GSTRH + ch) * 2,
                       &g_x[(size_t)(row0 + row) * K_TOT + k0 + ch]);
            CP_ASYNC16(dB + (uint32_t)(row * GSTRH + ch) * 2,
                       &g_wt[(size_t)(col0 + row) * K_TOT + k0 + ch]);
        }
    };

    issue(0, 0); CP_COMMIT();
    issue(1, 1); CP_COMMIT();

    for (int kt = 0; kt < GNKT; kt++) {
        CP_WAIT1();
        __syncthreads();
        const __half* As = smh + (kt % 3) * 2 * QSTH;
        const __half* Bs = As + QSTH;

#pragma unroll
        for (int ks = 0; ks < 2; ks++) {
            const int k0 = ks * 16;
            uint32_t af[4][4];
#pragma unroll
            for (int mi = 0; mi < 4; mi++) {
                const int r = (wm + mi * 16 + g) * GSTRH + k0 + 2 * t;
                af[mi][0] = *(const uint32_t*)&As[r];
                af[mi][1] = *(const uint32_t*)&As[r + 8 * GSTRH];
                af[mi][2] = *(const uint32_t*)&As[r + 8];
                af[mi][3] = *(const uint32_t*)&As[r + 8 * GSTRH + 8];
            }
            uint32_t bf[4][2];
#pragma unroll
            for (int ni = 0; ni < 4; ni++) {
                const int cn = (wn + ni * 8 + g) * GSTRH + k0 + 2 * t;
                bf[ni][0] = *(const uint32_t*)&Bs[cn];
                bf[ni][1] = *(const uint32_t*)&Bs[cn + 8];
            }
#pragma unroll
            for (int mi = 0; mi < 4; mi++)
#pragma unroll
                for (int ni = 0; ni < 4; ni++)
                    mma_f16(acc[mi][ni], af[mi], bf[ni][0], bf[ni][1]);
        }
        __syncthreads();
        if (kt + 2 < GNKT) issue((kt + 2) % 3, kt + 2);
        CP_COMMIT();
    }

    // Epilogue: fp16 round; Q/K -> [B,H,N,hd], V -> transposed [B,H,hd,N]
#pragma unroll
    for (int mi = 0; mi < 4; mi++) {
        const int row = row0 + wm + mi * 16 + g;
        const int b = row >> 11;
        const int n = row & (NN - 1);
#pragma unroll
        for (int ni = 0; ni < 4; ni++) {
            const int col = col0 + wn + ni * 8 + 2 * t;
            const int tt = col >> 10;
            const int h = (col >> 6) & 15;
            const int d = col & 63;
            const size_t bh = (size_t)(b * HH + h);
            if (tt < 2) {
                __half* base = (tt == 0) ? g_q : g_k;
                __half2* p0 = (__half2*)(base + (bh * NN + n) * HD + d);
                *p0 = __floats2half2_rn(acc[mi][ni][0], acc[mi][ni][1]);
                __half2* p1 = (__half2*)(base + (bh * NN + n + 8) * HD + d);
                *p1 = __floats2half2_rn(acc[mi][ni][2], acc[mi][ni][3]);
            } else {
                __half* vt = g_vt + bh * HD * NN;
                vt[(size_t)d * NN + n]           = __float2half_rn(acc[mi][ni][0]);
                vt[(size_t)(d + 1) * NN + n]     = __float2half_rn(acc[mi][ni][1]);
                vt[(size_t)d * NN + n + 8]       = __float2half_rn(acc[mi][ni][2]);
                vt[(size_t)(d + 1) * NN + n + 8] = __float2half_rn(acc[mi][ni][3]);
            }
        }
    }
}

// ---------------------------------------------------------------------------
// Kernel 3: Flash attention, mma.sync fp16 (m16n8k16).
// CTA = (b,h, 128 query rows); 4 warps x 32 rows (2 m16 tiles each).
// Key tiles of 64, double-buffered cp.async. P A-fragments are the packed
// S C-fragments (no shuffles, no smem). V is pre-transposed in gmem so PV
// B-fragments are contiguous half2 loads.
// ---------------------------------------------------------------------------
#define FBM 128
#define FBN 64
#define FNT (NN / FBN)     // 32
#define STRH 72            // halves per row (144B, conflict-free)
// byte offsets into dynamic smem
#define OFF_Q   0
#define OFF_K   (OFF_Q + FBM*STRH*2)          // 18432
#define OFF_VT  (OFF_K + 2*FBN*STRH*2)        // 36864
#define OFF_MQ  (OFF_VT + 2*FBN*STRH*2)       // 55296 (floats)
#define OFF_MK  (OFF_MQ + FBM*4)              // 55808
#define FSM_BYTES (OFF_MK + 2*FBN*4)          // 56320

__global__ __launch_bounds__(128, 2) void attn_mma_kernel(const float* __restrict__ mask,
                                                          float* __restrict__ out) {
    extern __shared__ char smc[];
    const uint32_t smb = smem_u32(smc);
    const uint32_t sQ  = smb + OFF_Q;
    const uint32_t sK  = smb + OFF_K;
    const uint32_t sVT = smb + OFF_VT;
    const uint32_t sMQ = smb + OFF_MQ;
    const uint32_t sMK = smb + OFF_MK;

    __half* Qs  = (__half*)(smc + OFF_Q);
    __half* Ks  = (__half*)(smc + OFF_K);
    __half* Vts = (__half*)(smc + OFF_VT);
    float*  mq  = (float*)(smc + OFF_MQ);
    float*  mk  = (float*)(smc + OFF_MK);

    const int bh = blockIdx.y;
    const int b  = bh >> 4;
    const int h  = bh & 15;
    const int r0 = blockIdx.x * FBM;

    const int tid  = threadIdx.x;
    const int wid  = tid >> 5;
    const int lane = tid & 31;
    const int g    = lane >> 2;
    const int t    = lane & 3;
    const int wm   = wid * 32;

    const __half* Qg  = g_q  + (size_t)bh * NN * HD;
    const __half* Kg  = g_k  + (size_t)bh * NN * HD;
    const __half* Vtg = g_vt + (size_t)bh * HD * NN;

    auto issue_kv = [&](int kt) {
        const int buf = kt & 1;
        const int c0 = kt * FBN;
#pragma unroll
        for (int p = 0; p < 4; p++) {
            int idx = p * 128 + tid;          // 512 chunks each
            int r = idx >> 3, ch = (idx & 7) * 8;
            CP_ASYNC16(sK + (uint32_t)((buf * FBN + r) * STRH + ch) * 2,
                       Kg + (size_t)(c0 + r) * HD + ch);
            CP_ASYNC16(sVT + (uint32_t)((buf * FBN + r) * STRH + ch) * 2,
                       Vtg + (size_t)r * NN + c0 + ch);
        }
        if (tid < 16)
            CP_ASYNC16(sMK + (uint32_t)(buf * FBN + tid * 4) * 4,
                       mask + (size_t)b * NN + c0 + tid * 4);
    };

    // Prologue: Q tile + row mask, then KV tiles 0 and 1
    {
#pragma unroll
        for (int p = 0; p < 8; p++) {
            int idx = p * 128 + tid;          // 1024 chunks
            int r = idx >> 3, ch = (idx & 7) * 8;
            CP_ASYNC16(sQ + (uint32_t)(r * STRH + ch) * 2,
                       Qg + (size_t)(r0 + r) * HD + ch);
        }
        if (tid < 32)
            CP_ASYNC16(sMQ + (uint32_t)(tid * 4) * 4,
                       mask + (size_t)b * NN + r0 + tid * 4);
        CP_COMMIT();
        issue_kv(0); CP_COMMIT();
        issue_kv(1); CP_COMMIT();
    }

    float o[2][8][4];
    float m_lo[2], m_hi[2], l_lo[2], l_hi[2];
#pragma unroll
    for (int mi = 0; mi < 2; mi++) {
        m_lo[mi] = -1e30f; m_hi[mi] = -1e30f;
        l_lo[mi] = 0.0f;   l_hi[mi] = 0.0f;
#pragma unroll
        for (int ni = 0; ni < 8; ni++)
#pragma unroll
            for (int j = 0; j < 4; j++) o[mi][ni][j] = 0.0f;
    }

    const float scale = 0.125f;   // 64^-0.5
    const uint32_t FULL = 0xffffffffu;

    for (int kt = 0; kt < FNT; kt++) {
        CP_WAIT1();
        __syncthreads();
        const int kb = (kt & 1) * FBN;

        // ---- S = Q K^T : 4 k16 steps ----
        float sA[2][8][4];
#pragma unroll
        for (int mi = 0; mi < 2; mi++)
#pragma unroll
            for (int ni = 0; ni < 8; ni++)
#pragma unroll
                for (int j = 0; j < 4; j++) sA[mi][ni][j] = 0.0f;

#pragma unroll
        for (int ks = 0; ks < 4; ks++) {
            const int k0 = ks * 16;
            uint32_t af[2][4];
#pragma unroll
            for (int mi = 0; mi < 2; mi++) {
                const int rq = (wm + mi * 16 + g) * STRH + k0 + 2 * t;
                af[mi][0] = *(const uint32_t*)&Qs[rq];
                af[mi][1] = *(const uint32_t*)&Qs[rq + 8 * STRH];
                af[mi][2] = *(const uint32_t*)&Qs[rq + 8];
                af[mi][3] = *(const uint32_t*)&Qs[rq + 8 * STRH + 8];
            }
#pragma unroll
            for (int ni = 0; ni < 8; ni++) {
                const int rk = (kb + ni * 8 + g) * STRH + k0 + 2 * t;
                const uint32_t b0 = *(const uint32_t*)&Ks[rk];
                const uint32_t b1 = *(const uint32_t*)&Ks[rk + 8];
                mma_f16(sA[0][ni], af[0], b0, b1);
                mma_f16(sA[1][ni], af[1], b0, b1);
            }
        }

        // ---- mask + online softmax ----
#pragma unroll
        for (int mi = 0; mi < 2; mi++) {
            const float mq_l = mq[wm + mi * 16 + g];
            const float mq_h = mq[wm + mi * 16 + g + 8];
            float mx_lo = -1e30f, mx_hi = -1e30f;
#pragma unroll
            for (int ni = 0; ni < 8; ni++) {
                const float k0v = mk[kb + ni * 8 + 2 * t];
                const float k1v = mk[kb + ni * 8 + 2 * t + 1];
                sA[mi][ni][0] = sA[mi][ni][0] * scale - mq_l * k0v;
                sA[mi][ni][1] = sA[mi][ni][1] * scale - mq_l * k1v;
                sA[mi][ni][2] = sA[mi][ni][2] * scale - mq_h * k0v;
                sA[mi][ni][3] = sA[mi][ni][3] * scale - mq_h * k1v;
                mx_lo = fmaxf(mx_lo, fmaxf(sA[mi][ni][0], sA[mi][ni][1]));
                mx_hi = fmaxf(mx_hi, fmaxf(sA[mi][ni][2], sA[mi][ni][3]));
            }
            mx_lo = fmaxf(mx_lo, __shfl_xor_sync(FULL, mx_lo, 1));
            mx_lo = fmaxf(mx_lo, __shfl_xor_sync(FULL, mx_lo, 2));
            mx_hi = fmaxf(mx_hi, __shfl_xor_sync(FULL, mx_hi, 1));
            mx_hi = fmaxf(mx_hi, __shfl_xor_sync(FULL, mx_hi, 2));

            const float mnew_lo = fmaxf(m_lo[mi], mx_lo);
            const float mnew_hi = fmaxf(m_hi[mi], mx_hi);
            const float fac_lo = __expf(m_lo[mi] - mnew_lo);
            const float fac_hi = __expf(m_hi[mi] - mnew_hi);

            float rs_lo = 0.0f, rs_hi = 0.0f;
#pragma unroll
            for (int ni = 0; ni < 8; ni++) {
                sA[mi][ni][0] = __expf(sA[mi][ni][0] - mnew_lo);
                sA[mi][ni][1] = __expf(sA[mi][ni][1] - mnew_lo);
                sA[mi][ni][2] = __expf(sA[mi][ni][2] - mnew_hi);
                sA[mi][ni][3] = __expf(sA[mi][ni][3] - mnew_hi);
                rs_lo += sA[mi][ni][0] + sA[mi][ni][1];
                rs_hi += sA[mi][ni][2] + sA[mi][ni][3];
            }
            rs_lo += __shfl_xor_sync(FULL, rs_lo, 1);
            rs_lo += __shfl_xor_sync(FULL, rs_lo, 2);
            rs_hi += __shfl_xor_sync(FULL, rs_hi, 1);
            rs_hi += __shfl_xor_sync(FULL, rs_hi, 2);

            l_lo[mi] = l_lo[mi] * fac_lo + rs_lo;  m_lo[mi] = mnew_lo;
            l_hi[mi] = l_hi[mi] * fac_hi + rs_hi;  m_hi[mi] = mnew_hi;
#pragma unroll
            for (int ni = 0; ni < 8; ni++) {
                o[mi][ni][0] *= fac_lo; o[mi][ni][1] *= fac_lo;
                o[mi][ni][2] *= fac_hi; o[mi][ni][3] *= fac_hi;
            }
        }

        // ---- O += P V : P A-fragments = packed S C-fragments; V from Vt smem ----
#pragma unroll
        for (int ks = 0; ks < 4; ks++) {
            uint32_t af[2][4];
#pragma unroll
            for (int mi = 0; mi < 2; mi++) {
                af[mi][0] = f2h2(sA[mi][2 * ks][0],     sA[mi][2 * ks][1]);
                af[mi][1] = f2h2(sA[mi][2 * ks][2],     sA[mi][2 * ks][3]);
                af[mi][2] = f2h2(sA[mi][2 * ks + 1][0], sA[mi][2 * ks + 1][1]);
                af[mi][3] = f2h2(sA[mi][2 * ks + 1][2], sA[mi][2 * ks + 1][3]);
            }
            const int k0 = ks * 16;
#pragma unroll
            for (int ni = 0; ni < 8; ni++) {
                const int rv = (kb + ni * 8 + g) * STRH + k0 + 2 * t;
                const uint32_t b0 = *(const uint32_t*)&Vts[rv];
                const uint32_t b1 = *(const uint32_t*)&Vts[rv + 8];
                mma_f16(o[0][ni], af[0], b0, b1);
                mma_f16(o[1][ni], af[1], b0, b1);
            }
        }

        __syncthreads();
        if (kt + 2 < FNT) issue_kv(kt + 2);
        CP_COMMIT();
    }

    // Output: out[b][n][h*64+d]
#pragma unroll
    for (int mi = 0; mi < 2; mi++) {
        const float inv_lo = 1.0f / l_lo[mi];
        const float inv_hi = 1.0f / l_hi[mi];
        const int row = r0 + wm + mi * 16 + g;
#pragma unroll
        for (int ni = 0; ni < 8; ni++) {
            const int col = h * HD + ni * 8 + 2 * t;
            *(float2*)&out[((size_t)(b * NN + row)) * CC + col] =
                make_float2(o[mi][ni][0] * inv_lo, o[mi][ni][1] * inv_lo);
            *(float2*)&out[((size_t)(b * NN + row + 8)) * CC + col] =
                make_float2(o[mi][ni][2] * inv_hi, o[mi][ni][3] * inv_hi);
        }
    }
}

// ---------------------------------------------------------------------------
extern "C" void kernel_launch(void* const* d_in, const int* in_sizes, int n_in,
                              void* d_out, int out_size) {
    const float* inputs = (const float*)d_in[0];   // [B,N,C]
    const float* mask   = (const float*)d_in[1];   // [B,N]
    const float* W      = (const float*)d_in[2];   // [C,3C]
    float* out = (float*)d_out;                    // [B,N,C]

    cudaFuncSetAttribute((const void*)qkv_mma_kernel,
                         cudaFuncAttributeMaxDynamicSharedMemorySize, QSM_BYTES);
    cudaFuncSetAttribute((const void*)attn_mma_kernel,
                         cudaFuncAttributeMaxDynamicSharedMemorySize, FSM_BYTES);

    pe_add_kernel<<<(NN * CC + 255) / 256, 256>>>(inputs);
    wt_kernel<<<dim3(N3C / 32, K_TOT / 32), dim3(32, 8)>>>(W);
    qkv_mma_kernel<<<dim3(N3C / GBN, M_TOT / GBM), 256, QSM_BYTES>>>();
    attn_mma_kernel<<<dim3(NN / FBM, BB * HH), 128, FSM_BYTES>>>(mask, out);
}

// round 7
// speedup vs baseline: 8.5804x; 1.0762x over previous
#include <cuda_runtime.h>
#include <cuda_fp16.h>
#include <math.h>
#include <stdint.h>

// Problem constants
#define BB 4
#define NN 2048
#define CC 1024
#define HH 16
#define HD 64
#define M_TOT (BB*NN)    // 8192
#define N3C   (3*CC)     // 3072
#define K_TOT CC         // 1024

#define LOG2E 1.4426950408889634f
#define QSCALE (0.125f * LOG2E)   // 64^-0.5 * log2(e), folded into Q

// Scratch (static device globals — allocation-free per harness rules)
__device__ __half g_x [M_TOT * CC];        // x = inputs + PE (fp16)  [8192,1024]
__device__ __half g_wt[N3C * CC];          // W^T (fp16)              [3072,1024]
__device__ __half g_q [BB*HH*NN*HD];       // [B,H,N,hd], pre-scaled by QSCALE
__device__ __half g_k [BB*HH*NN*HD];       // [B,H,N,hd]
__device__ __half g_vt[BB*HH*HD*NN];       // V transposed: [B,H,hd,N]

// ---------------------------------------------------------------------------
// Helpers
// ---------------------------------------------------------------------------
__device__ __forceinline__ void mma_f16(float* c, const uint32_t* a,
                                        uint32_t b0, uint32_t b1) {
    asm volatile(
        "mma.sync.aligned.m16n8k16.row.col.f32.f16.f16.f32 "
        "{%0,%1,%2,%3}, {%4,%5,%6,%7}, {%8,%9}, {%0,%1,%2,%3};"
        : "+f"(c[0]), "+f"(c[1]), "+f"(c[2]), "+f"(c[3])
        : "r"(a[0]), "r"(a[1]), "r"(a[2]), "r"(a[3]), "r"(b0), "r"(b1));
}

__device__ __forceinline__ uint32_t f2h2(float lo, float hi) {
    __half2 h = __floats2half2_rn(lo, hi);
    return *(uint32_t*)&h;
}

__device__ __forceinline__ float exp2f_fast(float x) {
    float y;
    asm("ex2.approx.ftz.f32 %0, %1;" : "=f"(y) : "f"(x));
    return y;
}

__device__ __forceinline__ uint32_t smem_u32(const void* p) {
    uint32_t a;
    asm("{ .reg .u64 t; cvta.to.shared.u64 t, %1; cvt.u32.u64 %0, t; }"
        : "=r"(a) : "l"(p));
    return a;
}

#define CP_ASYNC16(dst, src) \
    asm volatile("cp.async.cg.shared.global [%0], [%1], 16;" \
        :: "r"(dst), "l"(src) : "memory")
#define CP_COMMIT() asm volatile("cp.async.commit_group;" ::: "memory")
#define CP_WAIT1()  asm volatile("cp.async.wait_group 1;" ::: "memory")

// ---------------------------------------------------------------------------
// Kernel 1: x = inputs + sinusoidal PE -> fp16
// ---------------------------------------------------------------------------
__global__ void pe_add_kernel(const float* __restrict__ in) {
    int idx = blockIdx.x * blockDim.x + threadIdx.x;
    if (idx >= NN * CC) return;
    int c = idx & (CC - 1);
    int n = idx >> 10;
    float e = (float)(2 * (c >> 1)) / (float)CC;
    float rate = powf(10000.0f, -e);
    float ang = (float)n * rate;
    float s, co;
    sincosf(ang, &s, &co);
    float pe = (c & 1) ? co : s;
#pragma unroll
    for (int b = 0; b < BB; b++) {
        g_x[b * (NN * CC) + idx] = __float2half_rn(in[b * (NN * CC) + idx] + pe);
    }
}

// ---------------------------------------------------------------------------
// Kernel 1b: W^T -> fp16. W [1024,3072] -> g_wt [3072,1024]
// ---------------------------------------------------------------------------
__global__ __launch_bounds__(256) void wt_kernel(const float* __restrict__ W) {
    __shared__ float t[32][33];
    int tx = threadIdx.x, ty = threadIdx.y;
    int n0 = blockIdx.x * 32;
    int k0 = blockIdx.y * 32;
#pragma unroll
    for (int i = 0; i < 32; i += 8)
        t[ty + i][tx] = W[(size_t)(k0 + ty + i) * N3C + n0 + tx];
    __syncthreads();
#pragma unroll
    for (int i = 0; i < 32; i += 8)
        g_wt[(size_t)(n0 + ty + i) * K_TOT + k0 + tx] = __float2half_rn(t[tx][ty + i]);
}

// ---------------------------------------------------------------------------
// Kernel 2: QKV GEMM, mma.sync fp16 (m16n8k16), 3-stage cp.async pipeline.
// Epilogue: Q gets pre-scaled by QSCALE (log2-domain softmax); V transposed.
// ---------------------------------------------------------------------------
#define GBM 128
#define GBN 128
#define GBK 32
#define GSTRH 40                 // halves per row (80B, conflict-free)
#define GNKT (K_TOT / GBK)       // 32
#define QSTH (GBM * GSTRH)       // halves per tile per stage (5120)
#define QSM_BYTES (3 * 2 * QSTH * 2)   // 61440

__global__ __launch_bounds__(256, 2) void qkv_mma_kernel() {
    extern __shared__ char qsm[];
    const uint32_t smb = smem_u32(qsm);
    __half* smh = (__half*)qsm;

    const int tid  = threadIdx.x;
    const int wid  = tid >> 5;
    const int lane = tid & 31;
    const int g    = lane >> 2;    // 0..7
    const int t    = lane & 3;     // 0..3
    const int wm   = (wid & 1) * 64;
    const int wn   = (wid >> 1) * 32;
    const int row0 = blockIdx.y * GBM;
    const int col0 = blockIdx.x * GBN;

    float acc[4][4][4];
#pragma unroll
    for (int mi = 0; mi < 4; mi++)
#pragma unroll
        for (int ni = 0; ni < 4; ni++)
#pragma unroll
            for (int j = 0; j < 4; j++) acc[mi][ni][j] = 0.0f;

    auto issue = [&](int s, int kt) {
        const int k0 = kt * GBK;
        const uint32_t dA = smb + (uint32_t)(s * 2 * QSTH) * 2;
        const uint32_t dB = dA + (uint32_t)QSTH * 2;
#pragma unroll
        for (int p = 0; p < 2; p++) {
            int idx = p * 256 + tid;            // 512 chunks per tile
            int row = idx >> 2, ch = (idx & 3) * 8;
            CP_ASYNC16(dA + (uint32_t)(row * GSTRH + ch) * 2,
                       &g_x[(size_t)(row0 + row) * K_TOT + k0 + ch]);
            CP_ASYNC16(dB + (uint32_t)(row * GSTRH + ch) * 2,
                       &g_wt[(size_t)(col0 + row) * K_TOT + k0 + ch]);
        }
    };

    issue(0, 0); CP_COMMIT();
    issue(1, 1); CP_COMMIT();

    for (int kt = 0; kt < GNKT; kt++) {
        CP_WAIT1();
        __syncthreads();
        const __half* As = smh + (kt % 3) * 2 * QSTH;
        const __half* Bs = As + QSTH;

#pragma unroll
        for (int ks = 0; ks < 2; ks++) {
            const int k0 = ks * 16;
            uint32_t af[4][4];
#pragma unroll
            for (int mi = 0; mi < 4; mi++) {
                const int r = (wm + mi * 16 + g) * GSTRH + k0 + 2 * t;
                af[mi][0] = *(const uint32_t*)&As[r];
                af[mi][1] = *(const uint32_t*)&As[r + 8 * GSTRH];
                af[mi][2] = *(const uint32_t*)&As[r + 8];
                af[mi][3] = *(const uint32_t*)&As[r + 8 * GSTRH + 8];
            }
            uint32_t bf[4][2];
#pragma unroll
            for (int ni = 0; ni < 4; ni++) {
                const int cn = (wn + ni * 8 + g) * GSTRH + k0 + 2 * t;
                bf[ni][0] = *(const uint32_t*)&Bs[cn];
                bf[ni][1] = *(const uint32_t*)&Bs[cn + 8];
            }
#pragma unroll
            for (int mi = 0; mi < 4; mi++)
#pragma unroll
                for (int ni = 0; ni < 4; ni++)
                    mma_f16(acc[mi][ni], af[mi], bf[ni][0], bf[ni][1]);
        }
        __syncthreads();
        if (kt + 2 < GNKT) issue((kt + 2) % 3, kt + 2);
        CP_COMMIT();
    }

    // Epilogue: Q pre-scaled by QSCALE; Q/K -> [B,H,N,hd], V -> [B,H,hd,N]
#pragma unroll
    for (int mi = 0; mi < 4; mi++) {
        const int row = row0 + wm + mi * 16 + g;
        const int b = row >> 11;
        const int n = row & (NN - 1);
#pragma unroll
        for (int ni = 0; ni < 4; ni++) {
            const int col = col0 + wn + ni * 8 + 2 * t;
            const int tt = col >> 10;
            const int h = (col >> 6) & 15;
            const int d = col & 63;
            const size_t bh = (size_t)(b * HH + h);
            if (tt == 0) {
                __half2* p0 = (__half2*)(g_q + (bh * NN + n) * HD + d);
                *p0 = __floats2half2_rn(acc[mi][ni][0] * QSCALE, acc[mi][ni][1] * QSCALE);
                __half2* p1 = (__half2*)(g_q + (bh * NN + n + 8) * HD + d);
                *p1 = __floats2half2_rn(acc[mi][ni][2] * QSCALE, acc[mi][ni][3] * QSCALE);
            } else if (tt == 1) {
                __half2* p0 = (__half2*)(g_k + (bh * NN + n) * HD + d);
                *p0 = __floats2half2_rn(acc[mi][ni][0], acc[mi][ni][1]);
                __half2* p1 = (__half2*)(g_k + (bh * NN + n + 8) * HD + d);
                *p1 = __floats2half2_rn(acc[mi][ni][2], acc[mi][ni][3]);
            } else {
                __half* vt = g_vt + bh * HD * NN;
                vt[(size_t)d * NN + n]           = __float2half_rn(acc[mi][ni][0]);
                vt[(size_t)(d + 1) * NN + n]     = __float2half_rn(acc[mi][ni][1]);
                vt[(size_t)d * NN + n + 8]       = __float2half_rn(acc[mi][ni][2]);
                vt[(size_t)(d + 1) * NN + n + 8] = __float2half_rn(acc[mi][ni][3]);
            }
        }
    }
}

// ---------------------------------------------------------------------------
// Kernel 3: Flash attention, mma.sync fp16 (m16n8k16), log2-domain softmax.
// S arrives = (q.k)*scale*log2e (Q pre-scaled); mask = -mq*log2e*mk (1 fma);
// all exps via ex2.approx. P A-fragments = packed S C-fragments.
// ---------------------------------------------------------------------------
#define FBM 128
#define FBN 64
#define FNT (NN / FBN)     // 32
#define STRH 72            // halves per row (144B, conflict-free)
// byte offsets into dynamic smem
#define OFF_Q   0
#define OFF_K   (OFF_Q + FBM*STRH*2)          // 18432
#define OFF_VT  (OFF_K + 2*FBN*STRH*2)        // 36864
#define OFF_MQ  (OFF_VT + 2*FBN*STRH*2)       // 55296 (floats)
#define OFF_MK  (OFF_MQ + FBM*4)              // 55808
#define FSM_BYTES (OFF_MK + 2*FBN*4)          // 56320

__global__ __launch_bounds__(128, 2) void attn_mma_kernel(const float* __restrict__ mask,
                                                          float* __restrict__ out) {
    extern __shared__ char smc[];
    const uint32_t smb = smem_u32(smc);
    const uint32_t sQ  = smb + OFF_Q;
    const uint32_t sK  = smb + OFF_K;
    const uint32_t sVT = smb + OFF_VT;
    const uint32_t sMQ = smb + OFF_MQ;
    const uint32_t sMK = smb + OFF_MK;

    __half* Qs  = (__half*)(smc + OFF_Q);
    __half* Ks  = (__half*)(smc + OFF_K);
    __half* Vts = (__half*)(smc + OFF_VT);
    float*  mq  = (float*)(smc + OFF_MQ);
    float*  mk  = (float*)(smc + OFF_MK);

    const int bh = blockIdx.y;
    const int b  = bh >> 4;
    const int h  = bh & 15;
    const int r0 = blockIdx.x * FBM;

    const int tid  = threadIdx.x;
    const int wid  = tid >> 5;
    const int lane = tid & 31;
    const int g    = lane >> 2;
    const int t    = lane & 3;
    const int wm   = wid * 32;

    const __half* Qg  = g_q  + (size_t)bh * NN * HD;
    const __half* Kg  = g_k  + (size_t)bh * NN * HD;
    const __half* Vtg = g_vt + (size_t)bh * HD * NN;

    auto issue_kv = [&](int kt) {
        const int buf = kt & 1;
        const int c0 = kt * FBN;
#pragma unroll
        for (int p = 0; p < 4; p++) {
            int idx = p * 128 + tid;          // 512 chunks each
            int r = idx >> 3, ch = (idx & 7) * 8;
            CP_ASYNC16(sK + (uint32_t)((buf * FBN + r) * STRH + ch) * 2,
                       Kg + (size_t)(c0 + r) * HD + ch);
            CP_ASYNC16(sVT + (uint32_t)((buf * FBN + r) * STRH + ch) * 2,
                       Vtg + (size_t)r * NN + c0 + ch);
        }
        if (tid < 16)
            CP_ASYNC16(sMK + (uint32_t)(buf * FBN + tid * 4) * 4,
                       mask + (size_t)b * NN + c0 + tid * 4);
    };

    // Prologue: Q tile + row mask, then KV tiles 0 and 1
    {
#pragma unroll
        for (int p = 0; p < 8; p++) {
            int idx = p * 128 + tid;          // 1024 chunks
            int r = idx >> 3, ch = (idx & 7) * 8;
            CP_ASYNC16(sQ + (uint32_t)(r * STRH + ch) * 2,
                       Qg + (size_t)(r0 + r) * HD + ch);
        }
        if (tid < 32)
            CP_ASYNC16(sMQ + (uint32_t)(tid * 4) * 4,
                       mask + (size_t)b * NN + r0 + tid * 4);
        CP_COMMIT();
        issue_kv(0); CP_COMMIT();
        issue_kv(1); CP_COMMIT();
    }

    float o[2][8][4];
    float m_lo[2], m_hi[2], l_lo[2], l_hi[2];
#pragma unroll
    for (int mi = 0; mi < 2; mi++) {
        m_lo[mi] = -1e30f; m_hi[mi] = -1e30f;
        l_lo[mi] = 0.0f;   l_hi[mi] = 0.0f;
#pragma unroll
        for (int ni = 0; ni < 8; ni++)
#pragma unroll
            for (int j = 0; j < 4; j++) o[mi][ni][j] = 0.0f;
    }

    const uint32_t FULL = 0xffffffffu;

    for (int kt = 0; kt < FNT; kt++) {
        CP_WAIT1();
        __syncthreads();
        const int kb = (kt & 1) * FBN;

        // row-mask values (log2e-scaled) — mq constant per row
        const float mq_l2[2] = { mq[wm + g] * LOG2E,      mq[wm + 16 + g] * LOG2E };
        const float mq_h2[2] = { mq[wm + g + 8] * LOG2E,  mq[wm + 16 + g + 8] * LOG2E };
        // key-mask values, hoisted out of the mi loop
        float k0v[8], k1v[8];
#pragma unroll
        for (int ni = 0; ni < 8; ni++) {
            k0v[ni] = mk[kb + ni * 8 + 2 * t];
            k1v[ni] = mk[kb + ni * 8 + 2 * t + 1];
        }

        // ---- S = Q K^T : 4 k16 steps ----
        float sA[2][8][4];
#pragma unroll
        for (int mi = 0; mi < 2; mi++)
#pragma unroll
            for (int ni = 0; ni < 8; ni++)
#pragma unroll
                for (int j = 0; j < 4; j++) sA[mi][ni][j] = 0.0f;

#pragma unroll
        for (int ks = 0; ks < 4; ks++) {
            const int k0 = ks * 16;
            uint32_t af[2][4];
#pragma unroll
            for (int mi = 0; mi < 2; mi++) {
                const int rq = (wm + mi * 16 + g) * STRH + k0 + 2 * t;
                af[mi][0] = *(const uint32_t*)&Qs[rq];
                af[mi][1] = *(const uint32_t*)&Qs[rq + 8 * STRH];
                af[mi][2] = *(const uint32_t*)&Qs[rq + 8];
                af[mi][3] = *(const uint32_t*)&Qs[rq + 8 * STRH + 8];
            }
#pragma unroll
            for (int ni = 0; ni < 8; ni++) {
                const int rk = (kb + ni * 8 + g) * STRH + k0 + 2 * t;
                const uint32_t b0 = *(const uint32_t*)&Ks[rk];
                const uint32_t b1 = *(const uint32_t*)&Ks[rk + 8];
                mma_f16(sA[0][ni], af[0], b0, b1);
                mma_f16(sA[1][ni], af[1], b0, b1);
            }
        }

        // ---- mask (1 fma) + online softmax in log2 domain ----
#pragma unroll
        for (int mi = 0; mi < 2; mi++) {
            float mx_lo = -1e30f, mx_hi = -1e30f;
#pragma unroll
            for (int ni = 0; ni < 8; ni++) {
                sA[mi][ni][0] = fmaf(-mq_l2[mi], k0v[ni], sA[mi][ni][0]);
                sA[mi][ni][1] = fmaf(-mq_l2[mi], k1v[ni], sA[mi][ni][1]);
                sA[mi][ni][2] = fmaf(-mq_h2[mi], k0v[ni], sA[mi][ni][2]);
                sA[mi][ni][3] = fmaf(-mq_h2[mi], k1v[ni], sA[mi][ni][3]);
                mx_lo = fmaxf(mx_lo, fmaxf(sA[mi][ni][0], sA[mi][ni][1]));
                mx_hi = fmaxf(mx_hi, fmaxf(sA[mi][ni][2], sA[mi][ni][3]));
            }
            mx_lo = fmaxf(mx_lo, __shfl_xor_sync(FULL, mx_lo, 1));
            mx_lo = fmaxf(mx_lo, __shfl_xor_sync(FULL, mx_lo, 2));
            mx_hi = fmaxf(mx_hi, __shfl_xor_sync(FULL, mx_hi, 1));
            mx_hi = fmaxf(mx_hi, __shfl_xor_sync(FULL, mx_hi, 2));

            const float mnew_lo = fmaxf(m_lo[mi], mx_lo);
            const float mnew_hi = fmaxf(m_hi[mi], mx_hi);
            const float fac_lo = exp2f_fast(m_lo[mi] - mnew_lo);
            const float fac_hi = exp2f_fast(m_hi[mi] - mnew_hi);

            float rs_lo = 0.0f, rs_hi = 0.0f;
#pragma unroll
            for (int ni = 0; ni < 8; ni++) {
                sA[mi][ni][0] = exp2f_fast(sA[mi][ni][0] - mnew_lo);
                sA[mi][ni][1] = exp2f_fast(sA[mi][ni][1] - mnew_lo);
                sA[mi][ni][2] = exp2f_fast(sA[mi][ni][2] - mnew_hi);
                sA[mi][ni][3] = exp2f_fast(sA[mi][ni][3] - mnew_hi);
                rs_lo += sA[mi][ni][0] + sA[mi][ni][1];
                rs_hi += sA[mi][ni][2] + sA[mi][ni][3];
            }
            rs_lo += __shfl_xor_sync(FULL, rs_lo, 1);
            rs_lo += __shfl_xor_sync(FULL, rs_lo, 2);
            rs_hi += __shfl_xor_sync(FULL, rs_hi, 1);
            rs_hi += __shfl_xor_sync(FULL, rs_hi, 2);

            l_lo[mi] = fmaf(l_lo[mi], fac_lo, rs_lo);  m_lo[mi] = mnew_lo;
            l_hi[mi] = fmaf(l_hi[mi], fac_hi, rs_hi);  m_hi[mi] = mnew_hi;
#pragma unroll
            for (int ni = 0; ni < 8; ni++) {
                o[mi][ni][0] *= fac_lo; o[mi][ni][1] *= fac_lo;
                o[mi][ni][2] *= fac_hi; o[mi][ni][3] *= fac_hi;
            }
        }

        // ---- O += P V : P A-fragments = packed S C-fragments ----
#pragma unroll
        for (int ks = 0; ks < 4; ks++) {
            uint32_t af[2][4];
#pragma unroll
            for (int mi = 0; mi < 2; mi++) {
                af[mi][0] = f2h2(sA[mi][2 * ks][0],     sA[mi][2 * ks][1]);
                af[mi][1] = f2h2(sA[mi][2 * ks][2],     sA[mi][2 * ks][3]);
                af[mi][2] = f2h2(sA[mi][2 * ks + 1][0], sA[mi][2 * ks + 1][1]);
                af[mi][3] = f2h2(sA[mi][2 * ks + 1][2], sA[mi][2 * ks + 1][3]);
            }
            const int k0 = ks * 16;
#pragma unroll
            for (int ni = 0; ni < 8; ni++) {
                const int rv = (kb + ni * 8 + g) * STRH + k0 + 2 * t;
                const uint32_t b0 = *(const uint32_t*)&Vts[rv];
                const uint32_t b1 = *(const uint32_t*)&Vts[rv + 8];
                mma_f16(o[0][ni], af[0], b0, b1);
                mma_f16(o[1][ni], af[1], b0, b1);
            }
        }

        __syncthreads();
        if (kt + 2 < FNT) issue_kv(kt + 2);
        CP_COMMIT();
    }

    // Output: out[b][n][h*64+d]
#pragma unroll
    for (int mi = 0; mi < 2; mi++) {
        const float inv_lo = 1.0f / l_lo[mi];
        const float inv_hi = 1.0f / l_hi[mi];
        const int row = r0 + wm + mi * 16 + g;
#pragma unroll
        for (int ni = 0; ni < 8; ni++) {
            const int col = h * HD + ni * 8 + 2 * t;
            *(float2*)&out[((size_t)(b * NN + row)) * CC + col] =
                make_float2(o[mi][ni][0] * inv_lo, o[mi][ni][1] * inv_lo);
            *(float2*)&out[((size_t)(b * NN + row + 8)) * CC + col] =
                make_float2(o[mi][ni][2] * inv_hi, o[mi][ni][3] * inv_hi);
        }
    }
}

// ---------------------------------------------------------------------------
extern "C" void kernel_launch(void* const* d_in, const int* in_sizes, int n_in,
                              void* d_out, int out_size) {
    const float* inputs = (const float*)d_in[0];   // [B,N,C]
    const float* mask   = (const float*)d_in[1];   // [B,N]
    const float* W      = (const float*)d_in[2];   // [C,3C]
    float* out = (float*)d_out;                    // [B,N,C]

    cudaFuncSetAttribute((const void*)qkv_mma_kernel,
                         cudaFuncAttributeMaxDynamicSharedMemorySize, QSM_BYTES);
    cudaFuncSetAttribute((const void*)attn_mma_kernel,
                         cudaFuncAttributeMaxDynamicSharedMemorySize, FSM_BYTES);

    pe_add_kernel<<<(NN * CC + 255) / 256, 256>>>(inputs);
    wt_kernel<<<dim3(N3C / 32, K_TOT / 32), dim3(32, 8)>>>(W);
    qkv_mma_kernel<<<dim3(N3C / GBN, M_TOT / GBM), 256, QSM_BYTES>>>();
    attn_mma_kernel<<<dim3(NN / FBM, BB * HH), 128, FSM_BYTES>>>(mask, out);
}